// round 1
// baseline (speedup 1.0000x reference)
#include <cuda_runtime.h>

#define Tn    512
#define Bn    4
#define En    1024
#define Hn    16
#define HDn   64
#define NBn   32
#define TGTn  1536
#define BHn   64
#define Mrows (TGTn*Bn)   /* 6144 */

// -------- scratch (static device globals; no allocation allowed) --------
__device__ float g_q[(size_t)BHn*TGTn*HDn];
__device__ float g_k[(size_t)BHn*TGTn*HDn];
__device__ float g_v[(size_t)BHn*TGTn*HDn];
__device__ float g_vals[(size_t)Bn*TGTn*Hn*NBn];   // [b][tg][h][nb]
__device__ float g_ctx[(size_t)Mrows*En];          // pre-out-proj context, (TGT,B,E) rows

// ---------------------------------------------------------------------------
// Tiled SGEMM: C[m,n] = sum_k A[m,k] * Bm[n,k] + bias[n]
// BM=BN=64, BK=32, 256 threads, 4x4 microtile per thread.
// MODE 0: A := g_ctx (param ignored), C := d_out (plain store)
// MODE 1: qkv epilogue -> scatter into g_q (scaled by HD^-0.5) / g_k / g_v
// MODE 2: vals epilogue -> scatter into g_vals
// ---------------------------------------------------------------------------
template<int MODE>
__global__ __launch_bounds__(256) void sgemm_kernel(
    const float* __restrict__ A, const float* __restrict__ Bm,
    const float* __restrict__ bias, float* __restrict__ C,
    int M, int N, int K)
{
    __shared__ float sA[32*68];   // [k][m], stride 68
    __shared__ float sB[32*68];   // [k][n], stride 68
    const float* Ap = (MODE == 0) ? (const float*)g_ctx : A;

    int tid = threadIdx.x;
    int tx = tid & 15, ty = tid >> 4;
    int m0 = blockIdx.y * 64, n0 = blockIdx.x * 64;

    float acc[4][4] = {};

    for (int k0 = 0; k0 < K; k0 += 32) {
#pragma unroll
        for (int it = 0; it < 2; it++) {
            int f = tid + it * 256;            // 0..511 float4 slots
            int r = f >> 3, c4 = (f & 7) << 2; // row 0..63, k-col 0..28
            float4 va = *(const float4*)(Ap + (size_t)(m0 + r) * K + k0 + c4);
            sA[(c4+0)*68 + r] = va.x; sA[(c4+1)*68 + r] = va.y;
            sA[(c4+2)*68 + r] = va.z; sA[(c4+3)*68 + r] = va.w;
            float4 vb = *(const float4*)(Bm + (size_t)(n0 + r) * K + k0 + c4);
            sB[(c4+0)*68 + r] = vb.x; sB[(c4+1)*68 + r] = vb.y;
            sB[(c4+2)*68 + r] = vb.z; sB[(c4+3)*68 + r] = vb.w;
        }
        __syncthreads();
#pragma unroll
        for (int kk = 0; kk < 32; kk++) {
            float4 a = *(const float4*)(sA + kk*68 + ty*4);
            float4 b = *(const float4*)(sB + kk*68 + tx*4);
            acc[0][0]+=a.x*b.x; acc[0][1]+=a.x*b.y; acc[0][2]+=a.x*b.z; acc[0][3]+=a.x*b.w;
            acc[1][0]+=a.y*b.x; acc[1][1]+=a.y*b.y; acc[1][2]+=a.y*b.z; acc[1][3]+=a.y*b.w;
            acc[2][0]+=a.z*b.x; acc[2][1]+=a.z*b.y; acc[2][2]+=a.z*b.z; acc[2][3]+=a.z*b.w;
            acc[3][0]+=a.w*b.x; acc[3][1]+=a.w*b.y; acc[3][2]+=a.w*b.z; acc[3][3]+=a.w*b.w;
        }
        __syncthreads();
    }

#pragma unroll
    for (int i = 0; i < 4; i++) {
        int m = m0 + ty*4 + i;
#pragma unroll
        for (int j = 0; j < 4; j++) {
            int n = n0 + tx*4 + j;
            float v = acc[i][j] + bias[n];
            if (MODE == 0) {
                C[(size_t)m * N + n] = v;
            } else if (MODE == 1) {
                int tg = m >> 2, b = m & 3;        // m = tg*B + b
                int part = n >> 10, e = n & 1023;  // q/k/v
                int h = e >> 6, d = e & 63;
                float* dst = (part == 0) ? g_q : ((part == 1) ? g_k : g_v);
                if (part == 0) v *= 0.125f;        // HD^-0.5
                dst[((size_t)(b * Hn + h) * TGTn + tg) * HDn + d] = v;
            } else {
                int tg = m >> 2, b = m & 3;
                int nb = n >> 4, h = n & 15;       // j_col = nb*H + h
                g_vals[(((size_t)b * TGTn + tg) * Hn + h) * NBn + nb] = v;
            }
        }
    }
}

// ---------------------------------------------------------------------------
// Fused attention (flash-style, online softmax), TM=64 queries x BS=64 keys.
// grid = (8 qtiles, 64 bh, 3 variants): var 0 = main, var 1/2 = ngram 0/1.
// Ngram second-half mask is NEG*(1-eye) -> only the diagonal key survives;
// handled as one extra "virtual tile" whose key j is k_pred[t0+j], valid iff
// local col == local row.
// ---------------------------------------------------------------------------
#define SS 68   // shared row stride (bank-conflict-free float4 reads)

__global__ __launch_bounds__(256) void attn_kernel(
    const int* __restrict__ main_buckets,   // (B,T,T)
    const int* __restrict__ pred_buckets)   // (B,T,2T)
{
    extern __shared__ float sm[];
    float* sQ    = sm;               // [d][r] 64 x SS
    float* sK    = sm + 64*SS;       // [d][s]
    float* sV    = sm + 2*64*SS;     // [s][d]
    float* sP    = sm + 3*64*SS;     // [s][r]
    float* sVals = sm + 4*64*SS;     // [r][32]

    int tid = threadIdx.x;
    int tx = tid & 15, ty = tid >> 4;
    int tileX = blockIdx.x;          // 0..7
    int bh = blockIdx.y;             // 0..63
    int var = blockIdx.z;            // 0 main, 1..2 ngram
    int b = bh >> 4, h = bh & 15;
    int qoff = (var == 0) ? 0 : (Tn + (var - 1) * Tn);
    int t0 = tileX * 64;

    const float* qbase = g_q + ((size_t)bh * TGTn + qoff + t0) * HDn;
    const float* kbase = g_k + (size_t)bh * TGTn * HDn;
    const float* vbase = g_v + (size_t)bh * TGTn * HDn;

    // load Q tile (transposed [d][r])
#pragma unroll
    for (int it = 0; it < 4; it++) {
        int f = tid + it * 256;
        int r = f >> 4, d4 = (f & 15) << 2;
        float4 v = *(const float4*)(qbase + (size_t)r * HDn + d4);
        sQ[(d4+0)*SS + r] = v.x; sQ[(d4+1)*SS + r] = v.y;
        sQ[(d4+2)*SS + r] = v.z; sQ[(d4+3)*SS + r] = v.w;
    }
    // load rel-vals rows for this q tile: g_vals[b][qoff+t0+r][h][0..32)
    {
        const float* vrow = g_vals + (((size_t)b * TGTn + qoff + t0) * Hn + h) * NBn;
#pragma unroll
        for (int it = 0; it < 2; it++) {
            int f = tid + it * 256;
            int r = f >> 3, nb4 = (f & 7) << 2;
            *(float4*)(sVals + r * 32 + nb4) =
                *(const float4*)(vrow + (size_t)r * (Hn*NBn) + nb4);
        }
    }

    const int* brow;
    int bstride;
    if (var == 0) { brow = main_buckets + ((size_t)b * Tn + t0) * Tn;      bstride = Tn;   }
    else          { brow = pred_buckets + ((size_t)b * Tn + t0) * (2*Tn);  bstride = 2*Tn; }

    float mi[4], li[4], o[4][4];
#pragma unroll
    for (int i = 0; i < 4; i++) {
        mi[i] = -1e30f; li[i] = 0.f;
        o[i][0]=o[i][1]=o[i][2]=o[i][3]=0.f;
    }

    int nTiles = tileX + 1;                       // causal s-tiles
    int totTiles = nTiles + ((var != 0) ? 1 : 0); // + diagonal tile for ngram

    for (int st = 0; st < totTiles; st++) {
        bool extra = (st == nTiles);
        int s0 = st * 64;
        const float* kr = extra ? (kbase + (size_t)(qoff + t0) * HDn)
                                : (kbase + (size_t)s0 * HDn);
        const float* vr = extra ? (vbase + (size_t)(qoff + t0) * HDn)
                                : (vbase + (size_t)s0 * HDn);
        __syncthreads();   // previous tile fully consumed
#pragma unroll
        for (int it = 0; it < 4; it++) {
            int f = tid + it * 256;
            int r = f >> 4, d4 = (f & 15) << 2;
            float4 kv = *(const float4*)(kr + (size_t)r * HDn + d4);
            sK[(d4+0)*SS + r] = kv.x; sK[(d4+1)*SS + r] = kv.y;
            sK[(d4+2)*SS + r] = kv.z; sK[(d4+3)*SS + r] = kv.w;
            *(float4*)(sV + r * SS + d4) = *(const float4*)(vr + (size_t)r * HDn + d4);
        }
        __syncthreads();

        // scores: Q^T K over HD=64
        float sc[4][4] = {};
#pragma unroll
        for (int kk = 0; kk < 64; kk++) {
            float4 a  = *(const float4*)(sQ + kk*SS + ty*4);
            float4 bb = *(const float4*)(sK + kk*SS + tx*4);
            sc[0][0]+=a.x*bb.x; sc[0][1]+=a.x*bb.y; sc[0][2]+=a.x*bb.z; sc[0][3]+=a.x*bb.w;
            sc[1][0]+=a.y*bb.x; sc[1][1]+=a.y*bb.y; sc[1][2]+=a.y*bb.z; sc[1][3]+=a.y*bb.w;
            sc[2][0]+=a.z*bb.x; sc[2][1]+=a.z*bb.y; sc[2][2]+=a.z*bb.z; sc[2][3]+=a.z*bb.w;
            sc[3][0]+=a.w*bb.x; sc[3][1]+=a.w*bb.y; sc[3][2]+=a.w*bb.z; sc[3][3]+=a.w*bb.w;
        }

        // rel bias (bucket gather) + mask
#pragma unroll
        for (int i = 0; i < 4; i++) {
            int rloc = ty*4 + i;
            int t = t0 + rloc;
            int colb = extra ? (Tn + t0 + tx*4) : (s0 + tx*4);
            int4 bk = *(const int4*)(brow + (size_t)rloc * bstride + colb);
            int bka[4] = {bk.x, bk.y, bk.z, bk.w};
#pragma unroll
            for (int j = 0; j < 4; j++) {
                int cl = tx*4 + j;
                bool valid = extra ? (cl == rloc) : ((s0 + cl) <= t);
                sc[i][j] = valid ? (sc[i][j] + sVals[rloc*32 + bka[j]]) : -1e30f;
            }
        }

        // online softmax update (row reductions across the 16 tx lanes)
#pragma unroll
        for (int i = 0; i < 4; i++) {
            float tm = fmaxf(fmaxf(sc[i][0], sc[i][1]), fmaxf(sc[i][2], sc[i][3]));
#pragma unroll
            for (int off = 8; off > 0; off >>= 1)
                tm = fmaxf(tm, __shfl_xor_sync(0xffffffffu, tm, off));
            float mnew = fmaxf(mi[i], tm);
            float scale = __expf(mi[i] - mnew);
            float rs = 0.f;
#pragma unroll
            for (int j = 0; j < 4; j++) {
                float p = __expf(sc[i][j] - mnew);
                sc[i][j] = p; rs += p;
            }
#pragma unroll
            for (int off = 8; off > 0; off >>= 1)
                rs += __shfl_xor_sync(0xffffffffu, rs, off);
            li[i] = li[i] * scale + rs;
            mi[i] = mnew;
            o[i][0]*=scale; o[i][1]*=scale; o[i][2]*=scale; o[i][3]*=scale;
        }

        // stage P (transposed [s][r]) then P @ V
#pragma unroll
        for (int i = 0; i < 4; i++)
#pragma unroll
            for (int j = 0; j < 4; j++)
                sP[(tx*4+j)*SS + ty*4 + i] = sc[i][j];
        __syncthreads();
#pragma unroll
        for (int ss = 0; ss < 64; ss++) {
            float4 pa = *(const float4*)(sP + ss*SS + ty*4);
            float4 vb = *(const float4*)(sV + ss*SS + tx*4);
            o[0][0]+=pa.x*vb.x; o[0][1]+=pa.x*vb.y; o[0][2]+=pa.x*vb.z; o[0][3]+=pa.x*vb.w;
            o[1][0]+=pa.y*vb.x; o[1][1]+=pa.y*vb.y; o[1][2]+=pa.y*vb.z; o[1][3]+=pa.y*vb.w;
            o[2][0]+=pa.z*vb.x; o[2][1]+=pa.z*vb.y; o[2][2]+=pa.z*vb.z; o[2][3]+=pa.z*vb.w;
            o[3][0]+=pa.w*vb.x; o[3][1]+=pa.w*vb.y; o[3][2]+=pa.w*vb.z; o[3][3]+=pa.w*vb.w;
        }
    }

    // epilogue: ctx[(tg*B + b)][h*64 + d] = o / l
#pragma unroll
    for (int i = 0; i < 4; i++) {
        int tg = qoff + t0 + ty*4 + i;
        float inv = 1.0f / li[i];
        float4 r4;
        r4.x = o[i][0]*inv; r4.y = o[i][1]*inv; r4.z = o[i][2]*inv; r4.w = o[i][3]*inv;
        *(float4*)(g_ctx + ((size_t)tg * Bn + b) * En + h * HDn + tx*4) = r4;
    }
}

// ---------------------------------------------------------------------------
extern "C" void kernel_launch(void* const* d_in, const int* in_sizes, int n_in,
                              void* d_out, int out_size) {
    const float* query = (const float*)d_in[0];
    const float* ipw   = (const float*)d_in[1];
    const float* ipb   = (const float*)d_in[2];
    const float* relw  = (const float*)d_in[3];
    const float* relb  = (const float*)d_in[4];
    const float* outw  = (const float*)d_in[5];
    const float* outb  = (const float*)d_in[6];
    const int*   mb    = (const int*)d_in[7];
    const int*   pb    = (const int*)d_in[8];
    float* out = (float*)d_out;

    const int attn_smem = 4*64*SS*4 + 64*32*4;   // 4 tiles + vals = 77824 B
    cudaFuncSetAttribute(attn_kernel,
                         cudaFuncAttributeMaxDynamicSharedMemorySize, attn_smem);

    // 1) qkv projection + head scatter (q scaled)
    sgemm_kernel<1><<<dim3(48, 96), 256>>>(query, ipw, ipb, nullptr, Mrows, 3*En, En);
    // 2) rel-bucket value table for all TGT rows
    sgemm_kernel<2><<<dim3(8, 96), 256>>>(query, relw, relb, nullptr, Mrows, NBn*Hn, En);
    // 3) fused attention (main + 2 ngram streams)
    attn_kernel<<<dim3(8, 64, 3), 256, attn_smem>>>(mb, pb);
    // 4) output projection -> d_out
    sgemm_kernel<0><<<dim3(16, 96), 256>>>(nullptr, outw, outb, out, Mrows, En, En);
}

// round 3
// speedup vs baseline: 3.8715x; 3.8715x over previous
#include <cuda_runtime.h>
#include <cuda_fp16.h>
#include <cstdint>

#define Tn    512
#define Bn    4
#define En    1024
#define Hn    16
#define HDn   64
#define NBn   32
#define TGTn  1536
#define BHn   64
#define Mrows (TGTn*Bn)   /* 6144 */

// -------- scratch (static device globals; no allocation allowed) --------
__device__ float g_q[(size_t)BHn*TGTn*HDn];
__device__ float g_k[(size_t)BHn*TGTn*HDn];
__device__ float g_v[(size_t)BHn*TGTn*HDn];
__device__ float g_vals[(size_t)Bn*TGTn*Hn*NBn];   // [b][tg][h][nb]
__device__ float g_ctx[(size_t)Mrows*En];          // pre-out-proj context

// ============================ helpers ==================================
__device__ __forceinline__ uint32_t smem_u32(const void* p) {
    uint32_t a;
    asm("{ .reg .u64 t; cvta.to.shared.u64 t, %1; cvt.u32.u64 %0, t; }"
        : "=r"(a) : "l"(p));
    return a;
}
__device__ __forceinline__ void ldsm4(uint32_t* r, uint32_t addr) {
    asm volatile("ldmatrix.sync.aligned.m8n8.x4.shared.b16 {%0,%1,%2,%3}, [%4];"
                 : "=r"(r[0]), "=r"(r[1]), "=r"(r[2]), "=r"(r[3]) : "r"(addr));
}
__device__ __forceinline__ void mma16816(float* c, const uint32_t* a, const uint32_t* b) {
    asm volatile(
        "mma.sync.aligned.m16n8k16.row.col.f32.f16.f16.f32 "
        "{%0,%1,%2,%3}, {%4,%5,%6,%7}, {%8,%9}, {%0,%1,%2,%3};"
        : "+f"(c[0]), "+f"(c[1]), "+f"(c[2]), "+f"(c[3])
        : "r"(a[0]), "r"(a[1]), "r"(a[2]), "r"(a[3]), "r"(b[0]), "r"(b[1]));
}
// split two floats into fp16 hi pair + fp16 residual pair (packed b32)
__device__ __forceinline__ void split2(float x, float y, uint32_t& hi, uint32_t& lo) {
    __half hx = __float2half_rn(x), hy = __float2half_rn(y);
    __half lx = __float2half_rn(x - __half2float(hx));
    __half ly = __float2half_rn(y - __half2float(hy));
    __half2 h = __halves2half2(hx, hy), l = __halves2half2(lx, ly);
    hi = *(uint32_t*)&h; lo = *(uint32_t*)&l;
}

// ---------------------------------------------------------------------------
// HMMA GEMM (fp16 split, 3 passes): C[m,n] = sum_k A[m,k]*Bm[n,k] + bias[n]
// BM=BN=128, BK=32, 256 threads (8 warps, 2x4 warp grid, 64x32 warp tile).
// MODE 0: A := g_ctx, C := d_out
// MODE 1: qkv epilogue -> g_q (scaled) / g_k / g_v
// MODE 2: vals epilogue -> g_vals
// ---------------------------------------------------------------------------
#define RS 80                 // smem row stride in bytes (32 fp16 + pad)
#define TILE_BYTES (128*RS)   // 10240

template<int MODE>
__global__ __launch_bounds__(256, 2) void hgemm_kernel(
    const float* __restrict__ A, const float* __restrict__ Bm,
    const float* __restrict__ bias, float* __restrict__ C,
    int M, int N, int K)
{
    __shared__ __align__(16) char smem[4*TILE_BYTES];   // Ah, Al, Bh, Bl
    char* sAh = smem;
    char* sAl = smem + TILE_BYTES;
    char* sBh = smem + 2*TILE_BYTES;
    char* sBl = smem + 3*TILE_BYTES;
    const float* Ap = (MODE == 0) ? (const float*)g_ctx : A;

    int tid = threadIdx.x;
    int lane = tid & 31, wid = tid >> 5;
    int wm = wid & 1, wn = wid >> 1;          // warp grid: 2 (M) x 4 (N)
    int m0 = blockIdx.y * 128, n0 = blockIdx.x * 128;

    // ldmatrix per-lane address components
    int rowA = (lane & 7) + ((lane >> 3) & 1) * 8;
    int colA = ((lane >> 4) & 1) * 16;
    int rowB = (lane & 7) + ((lane >> 4) & 1) * 8;
    int colB = ((lane >> 3) & 1) * 16;
    uint32_t aAh = smem_u32(sAh) + (uint32_t)((wm*64 + rowA) * RS + colA);
    uint32_t aAl = aAh + TILE_BYTES;
    uint32_t aBh = smem_u32(sBh) + (uint32_t)((wn*32 + rowB) * RS + colB);
    uint32_t aBl = aBh + TILE_BYTES;

    float acc[16][4];
#pragma unroll
    for (int i = 0; i < 16; i++) { acc[i][0]=acc[i][1]=acc[i][2]=acc[i][3]=0.f; }

    for (int k0 = 0; k0 < K; k0 += 32) {
        // ---- load + split-convert A tile (128 x 32 f32) ----
#pragma unroll
        for (int it = 0; it < 4; it++) {
            int f = tid + it * 256;            // 1024 float4 slots
            int r = f >> 3, c4 = (f & 7) << 2;
            float4 v = *(const float4*)(Ap + (size_t)(m0 + r) * K + k0 + c4);
            uint32_t h01, l01, h23, l23;
            split2(v.x, v.y, h01, l01);
            split2(v.z, v.w, h23, l23);
            int off = r * RS + c4 * 2;
            *(uint2*)(sAh + off) = make_uint2(h01, h23);
            *(uint2*)(sAl + off) = make_uint2(l01, l23);
        }
        // ---- load + split-convert B tile ----
#pragma unroll
        for (int it = 0; it < 4; it++) {
            int f = tid + it * 256;
            int r = f >> 3, c4 = (f & 7) << 2;
            float4 v = *(const float4*)(Bm + (size_t)(n0 + r) * K + k0 + c4);
            uint32_t h01, l01, h23, l23;
            split2(v.x, v.y, h01, l01);
            split2(v.z, v.w, h23, l23);
            int off = r * RS + c4 * 2;
            *(uint2*)(sBh + off) = make_uint2(h01, h23);
            *(uint2*)(sBl + off) = make_uint2(l01, l23);
        }
        __syncthreads();

#pragma unroll
        for (int ks = 0; ks < 2; ks++) {
            // B fragments: hi + lo (x4 covers two n-tiles)
            uint32_t bh[4][2], bl[4][2];
#pragma unroll
            for (int np = 0; np < 2; np++) {
                uint32_t t[4];
                ldsm4(t, aBh + np * (16*RS) + ks * 32);
                bh[2*np][0]=t[0]; bh[2*np][1]=t[1];
                bh[2*np+1][0]=t[2]; bh[2*np+1][1]=t[3];
                ldsm4(t, aBl + np * (16*RS) + ks * 32);
                bl[2*np][0]=t[0]; bl[2*np][1]=t[1];
                bl[2*np+1][0]=t[2]; bl[2*np+1][1]=t[3];
            }
            uint32_t a[4][4];
            // pass 1+2: Ahi * (Bhi, Blo)
#pragma unroll
            for (int mt = 0; mt < 4; mt++)
                ldsm4(a[mt], aAh + mt * (16*RS) + ks * 32);
#pragma unroll
            for (int mt = 0; mt < 4; mt++)
#pragma unroll
                for (int nt = 0; nt < 4; nt++)
                    mma16816(acc[mt*4+nt], a[mt], bh[nt]);
#pragma unroll
            for (int mt = 0; mt < 4; mt++)
#pragma unroll
                for (int nt = 0; nt < 4; nt++)
                    mma16816(acc[mt*4+nt], a[mt], bl[nt]);
            // pass 3: Alo * Bhi
#pragma unroll
            for (int mt = 0; mt < 4; mt++)
                ldsm4(a[mt], aAl + mt * (16*RS) + ks * 32);
#pragma unroll
            for (int mt = 0; mt < 4; mt++)
#pragma unroll
                for (int nt = 0; nt < 4; nt++)
                    mma16816(acc[mt*4+nt], a[mt], bh[nt]);
        }
        __syncthreads();
    }

    // ---- epilogue: fragment scatter ----
#pragma unroll
    for (int mt = 0; mt < 4; mt++) {
        int mbase = m0 + wm*64 + mt*16 + (lane >> 2);
#pragma unroll
        for (int nt = 0; nt < 4; nt++) {
            int nbase = n0 + wn*32 + nt*8 + (lane & 3) * 2;
            float* ac = acc[mt*4+nt];
#pragma unroll
            for (int rr = 0; rr < 4; rr++) {
                int m = mbase + (rr >> 1) * 8;
                int n = nbase + (rr & 1);
                float v = ac[rr] + bias[n];
                if (MODE == 0) {
                    C[(size_t)m * N + n] = v;
                } else if (MODE == 1) {
                    int tg = m >> 2, b = m & 3;        // m = tg*B + b
                    int part = n >> 10, e = n & 1023;
                    int h = e >> 6, dd = e & 63;
                    float* dst = (part == 0) ? g_q : ((part == 1) ? g_k : g_v);
                    if (part == 0) v *= 0.125f;        // HD^-0.5
                    dst[((size_t)(b * Hn + h) * TGTn + tg) * HDn + dd] = v;
                } else {
                    int tg = m >> 2, b = m & 3;
                    int nb = n >> 4, h = n & 15;       // col = nb*H + h
                    g_vals[(((size_t)b * TGTn + tg) * Hn + h) * NBn + nb] = v;
                }
            }
        }
    }
}

// ---------------------------------------------------------------------------
// Fused attention (flash-style, online softmax) — unchanged from Round 1.
// ---------------------------------------------------------------------------
#define SS 68   // shared row stride

__global__ __launch_bounds__(256) void attn_kernel(
    const int* __restrict__ main_buckets,   // (B,T,T)
    const int* __restrict__ pred_buckets)   // (B,T,2T)
{
    extern __shared__ float sm[];
    float* sQ    = sm;               // [d][r] 64 x SS
    float* sK    = sm + 64*SS;       // [d][s]
    float* sV    = sm + 2*64*SS;     // [s][d]
    float* sP    = sm + 3*64*SS;     // [s][r]
    float* sVals = sm + 4*64*SS;     // [r][32]

    int tid = threadIdx.x;
    int tx = tid & 15, ty = tid >> 4;
    int tileX = blockIdx.x;
    int bh = blockIdx.y;
    int var = blockIdx.z;
    int b = bh >> 4, h = bh & 15;
    int qoff = (var == 0) ? 0 : (Tn + (var - 1) * Tn);
    int t0 = tileX * 64;

    const float* qbase = g_q + ((size_t)bh * TGTn + qoff + t0) * HDn;
    const float* kbase = g_k + (size_t)bh * TGTn * HDn;
    const float* vbase = g_v + (size_t)bh * TGTn * HDn;

#pragma unroll
    for (int it = 0; it < 4; it++) {
        int f = tid + it * 256;
        int r = f >> 4, d4 = (f & 15) << 2;
        float4 v = *(const float4*)(qbase + (size_t)r * HDn + d4);
        sQ[(d4+0)*SS + r] = v.x; sQ[(d4+1)*SS + r] = v.y;
        sQ[(d4+2)*SS + r] = v.z; sQ[(d4+3)*SS + r] = v.w;
    }
    {
        const float* vrow = g_vals + (((size_t)b * TGTn + qoff + t0) * Hn + h) * NBn;
#pragma unroll
        for (int it = 0; it < 2; it++) {
            int f = tid + it * 256;
            int r = f >> 3, nb4 = (f & 7) << 2;
            *(float4*)(sVals + r * 32 + nb4) =
                *(const float4*)(vrow + (size_t)r * (Hn*NBn) + nb4);
        }
    }

    const int* brow;
    int bstride;
    if (var == 0) { brow = main_buckets + ((size_t)b * Tn + t0) * Tn;      bstride = Tn;   }
    else          { brow = pred_buckets + ((size_t)b * Tn + t0) * (2*Tn);  bstride = 2*Tn; }

    float mi[4], li[4], o[4][4];
#pragma unroll
    for (int i = 0; i < 4; i++) {
        mi[i] = -1e30f; li[i] = 0.f;
        o[i][0]=o[i][1]=o[i][2]=o[i][3]=0.f;
    }

    int nTiles = tileX + 1;
    int totTiles = nTiles + ((var != 0) ? 1 : 0);

    for (int st = 0; st < totTiles; st++) {
        bool extra = (st == nTiles);
        int s0 = st * 64;
        const float* kr = extra ? (kbase + (size_t)(qoff + t0) * HDn)
                                : (kbase + (size_t)s0 * HDn);
        const float* vr = extra ? (vbase + (size_t)(qoff + t0) * HDn)
                                : (vbase + (size_t)s0 * HDn);
        __syncthreads();
#pragma unroll
        for (int it = 0; it < 4; it++) {
            int f = tid + it * 256;
            int r = f >> 4, d4 = (f & 15) << 2;
            float4 kv = *(const float4*)(kr + (size_t)r * HDn + d4);
            sK[(d4+0)*SS + r] = kv.x; sK[(d4+1)*SS + r] = kv.y;
            sK[(d4+2)*SS + r] = kv.z; sK[(d4+3)*SS + r] = kv.w;
            *(float4*)(sV + r * SS + d4) = *(const float4*)(vr + (size_t)r * HDn + d4);
        }
        __syncthreads();

        float sc[4][4] = {};
#pragma unroll
        for (int kk = 0; kk < 64; kk++) {
            float4 a  = *(const float4*)(sQ + kk*SS + ty*4);
            float4 bb = *(const float4*)(sK + kk*SS + tx*4);
            sc[0][0]+=a.x*bb.x; sc[0][1]+=a.x*bb.y; sc[0][2]+=a.x*bb.z; sc[0][3]+=a.x*bb.w;
            sc[1][0]+=a.y*bb.x; sc[1][1]+=a.y*bb.y; sc[1][2]+=a.y*bb.z; sc[1][3]+=a.y*bb.w;
            sc[2][0]+=a.z*bb.x; sc[2][1]+=a.z*bb.y; sc[2][2]+=a.z*bb.z; sc[2][3]+=a.z*bb.w;
            sc[3][0]+=a.w*bb.x; sc[3][1]+=a.w*bb.y; sc[3][2]+=a.w*bb.z; sc[3][3]+=a.w*bb.w;
        }

#pragma unroll
        for (int i = 0; i < 4; i++) {
            int rloc = ty*4 + i;
            int t = t0 + rloc;
            int colb = extra ? (Tn + t0 + tx*4) : (s0 + tx*4);
            int4 bk = *(const int4*)(brow + (size_t)rloc * bstride + colb);
            int bka[4] = {bk.x, bk.y, bk.z, bk.w};
#pragma unroll
            for (int j = 0; j < 4; j++) {
                int cl = tx*4 + j;
                bool valid = extra ? (cl == rloc) : ((s0 + cl) <= t);
                sc[i][j] = valid ? (sc[i][j] + sVals[rloc*32 + bka[j]]) : -1e30f;
            }
        }

#pragma unroll
        for (int i = 0; i < 4; i++) {
            float tm = fmaxf(fmaxf(sc[i][0], sc[i][1]), fmaxf(sc[i][2], sc[i][3]));
#pragma unroll
            for (int off = 8; off > 0; off >>= 1)
                tm = fmaxf(tm, __shfl_xor_sync(0xffffffffu, tm, off));
            float mnew = fmaxf(mi[i], tm);
            float scale = __expf(mi[i] - mnew);
            float rs = 0.f;
#pragma unroll
            for (int j = 0; j < 4; j++) {
                float p = __expf(sc[i][j] - mnew);
                sc[i][j] = p; rs += p;
            }
#pragma unroll
            for (int off = 8; off > 0; off >>= 1)
                rs += __shfl_xor_sync(0xffffffffu, rs, off);
            li[i] = li[i] * scale + rs;
            mi[i] = mnew;
            o[i][0]*=scale; o[i][1]*=scale; o[i][2]*=scale; o[i][3]*=scale;
        }

#pragma unroll
        for (int i = 0; i < 4; i++)
#pragma unroll
            for (int j = 0; j < 4; j++)
                sP[(tx*4+j)*SS + ty*4 + i] = sc[i][j];
        __syncthreads();
#pragma unroll
        for (int ss = 0; ss < 64; ss++) {
            float4 pa = *(const float4*)(sP + ss*SS + ty*4);
            float4 vb = *(const float4*)(sV + ss*SS + tx*4);
            o[0][0]+=pa.x*vb.x; o[0][1]+=pa.x*vb.y; o[0][2]+=pa.x*vb.z; o[0][3]+=pa.x*vb.w;
            o[1][0]+=pa.y*vb.x; o[1][1]+=pa.y*vb.y; o[1][2]+=pa.y*vb.z; o[1][3]+=pa.y*vb.w;
            o[2][0]+=pa.z*vb.x; o[2][1]+=pa.z*vb.y; o[2][2]+=pa.z*vb.z; o[2][3]+=pa.z*vb.w;
            o[3][0]+=pa.w*vb.x; o[3][1]+=pa.w*vb.y; o[3][2]+=pa.w*vb.z; o[3][3]+=pa.w*vb.w;
        }
    }

#pragma unroll
    for (int i = 0; i < 4; i++) {
        int tg = qoff + t0 + ty*4 + i;
        float inv = 1.0f / li[i];
        float4 r4;
        r4.x = o[i][0]*inv; r4.y = o[i][1]*inv; r4.z = o[i][2]*inv; r4.w = o[i][3]*inv;
        *(float4*)(g_ctx + ((size_t)tg * Bn + b) * En + h * HDn + tx*4) = r4;
    }
}

// ---------------------------------------------------------------------------
extern "C" void kernel_launch(void* const* d_in, const int* in_sizes, int n_in,
                              void* d_out, int out_size) {
    const float* query = (const float*)d_in[0];
    const float* ipw   = (const float*)d_in[1];
    const float* ipb   = (const float*)d_in[2];
    const float* relw  = (const float*)d_in[3];
    const float* relb  = (const float*)d_in[4];
    const float* outw  = (const float*)d_in[5];
    const float* outb  = (const float*)d_in[6];
    const int*   mb    = (const int*)d_in[7];
    const int*   pb    = (const int*)d_in[8];
    float* out = (float*)d_out;

    const int attn_smem = 4*64*SS*4 + 64*32*4;   // 77824 B
    cudaFuncSetAttribute(attn_kernel,
                         cudaFuncAttributeMaxDynamicSharedMemorySize, attn_smem);

    // 1) qkv projection + head scatter (q scaled)   M=6144 N=3072 K=1024
    hgemm_kernel<1><<<dim3(24, 48), 256>>>(query, ipw, ipb, nullptr, Mrows, 3*En, En);
    // 2) rel-bucket value table                     M=6144 N=512  K=1024
    hgemm_kernel<2><<<dim3(4, 48), 256>>>(query, relw, relb, nullptr, Mrows, NBn*Hn, En);
    // 3) fused attention (main + 2 ngram streams)
    attn_kernel<<<dim3(8, 64, 3), 256, attn_smem>>>(mb, pb);
    // 4) output projection -> d_out                 M=6144 N=1024 K=1024
    hgemm_kernel<0><<<dim3(8, 48), 256>>>(nullptr, outw, outb, out, Mrows, En, En);
}

// round 6
// speedup vs baseline: 4.1986x; 1.0845x over previous
#include <cuda_runtime.h>
#include <cuda_fp16.h>
#include <cstdint>

#define Tn    512
#define Bn    4
#define En    1024
#define Hn    16
#define HDn   64
#define NBn   32
#define TGTn  1536
#define BHn   64
#define Mrows (TGTn*Bn)   /* 6144 */

// -------- scratch (static device globals) --------
__device__ __half g_x_h[(size_t)Mrows*En],    g_x_l[(size_t)Mrows*En];
__device__ __half g_ipw_h[(size_t)3*En*En],   g_ipw_l[(size_t)3*En*En];
__device__ __half g_relw_h[(size_t)NBn*Hn*En],g_relw_l[(size_t)NBn*Hn*En];
__device__ __half g_outw_h[(size_t)En*En],    g_outw_l[(size_t)En*En];
__device__ __half g_ctx_h[(size_t)Mrows*En],  g_ctx_l[(size_t)Mrows*En];
__device__ __half g_q_h[(size_t)BHn*TGTn*HDn], g_q_l[(size_t)BHn*TGTn*HDn];
__device__ __half g_k_h[(size_t)BHn*TGTn*HDn], g_k_l[(size_t)BHn*TGTn*HDn];
__device__ __half g_v_h[(size_t)BHn*TGTn*HDn], g_v_l[(size_t)BHn*TGTn*HDn];
__device__ float  g_vals[(size_t)Bn*TGTn*Hn*NBn];   // [b][tg][h][nb]

// ============================ helpers ==================================
__device__ __forceinline__ uint32_t smem_u32(const void* p) {
    uint32_t a;
    asm("{ .reg .u64 t; cvta.to.shared.u64 t, %1; cvt.u32.u64 %0, t; }"
        : "=r"(a) : "l"(p));
    return a;
}
__device__ __forceinline__ void ldsm4(uint32_t* r, uint32_t addr) {
    asm volatile("ldmatrix.sync.aligned.m8n8.x4.shared.b16 {%0,%1,%2,%3}, [%4];"
                 : "=r"(r[0]), "=r"(r[1]), "=r"(r[2]), "=r"(r[3]) : "r"(addr));
}
__device__ __forceinline__ void ldsm4t(uint32_t* r, uint32_t addr) {
    asm volatile("ldmatrix.sync.aligned.m8n8.x4.trans.shared.b16 {%0,%1,%2,%3}, [%4];"
                 : "=r"(r[0]), "=r"(r[1]), "=r"(r[2]), "=r"(r[3]) : "r"(addr));
}
__device__ __forceinline__ void mma16816(float* c, const uint32_t* a, const uint32_t* b) {
    asm volatile(
        "mma.sync.aligned.m16n8k16.row.col.f32.f16.f16.f32 "
        "{%0,%1,%2,%3}, {%4,%5,%6,%7}, {%8,%9}, {%0,%1,%2,%3};"
        : "+f"(c[0]), "+f"(c[1]), "+f"(c[2]), "+f"(c[3])
        : "r"(a[0]), "r"(a[1]), "r"(a[2]), "r"(a[3]), "r"(b[0]), "r"(b[1]));
}
__device__ __forceinline__ void cp16(uint32_t dst, const void* src) {
    asm volatile("cp.async.cg.shared.global [%0], [%1], 16;"
                 :: "r"(dst), "l"(src) : "memory");
}
#define CP_COMMIT() asm volatile("cp.async.commit_group;" ::: "memory")
#define CP_WAIT(N)  asm volatile("cp.async.wait_group %0;" :: "n"(N) : "memory")

// split two floats into fp16 hi pair + fp16 residual pair (packed b32)
__device__ __forceinline__ void split2(float x, float y, uint32_t& hi, uint32_t& lo) {
    __half hx = __float2half_rn(x), hy = __float2half_rn(y);
    __half lx = __float2half_rn(x - __half2float(hx));
    __half ly = __float2half_rn(y - __half2float(hy));
    __half2 h = __halves2half2(hx, hy), l = __halves2half2(lx, ly);
    hi = *(uint32_t*)&h; lo = *(uint32_t*)&l;
}

// ---------------------------------------------------------------------------
// Pre-convert f32 -> fp16 hi/lo global buffers. mode: 0=x 1=ipw 2=relw 3=outw
// ---------------------------------------------------------------------------
__global__ __launch_bounds__(256) void convert_kernel(
    const float* __restrict__ src, int n, int mode)
{
    int i = (blockIdx.x * 256 + threadIdx.x) * 4;
    if (i >= n) return;
    float4 v = *(const float4*)(src + i);
    uint32_t h01, l01, h23, l23;
    split2(v.x, v.y, h01, l01);
    split2(v.z, v.w, h23, l23);
    __half *dh, *dl;
    switch (mode) {
        case 0:  dh = g_x_h;    dl = g_x_l;    break;
        case 1:  dh = g_ipw_h;  dl = g_ipw_l;  break;
        case 2:  dh = g_relw_h; dl = g_relw_l; break;
        default: dh = g_outw_h; dl = g_outw_l; break;
    }
    *(uint2*)(dh + i) = make_uint2(h01, h23);
    *(uint2*)(dl + i) = make_uint2(l01, l23);
}

// ---------------------------------------------------------------------------
// HMMA GEMM v2 (fp16 split 3-pass, cp.async 2-stage): C = A*B^T + bias
// BM=BN=128, BK=32, 256 threads. Operands selected by MODE (global fp16).
// MODE 0: A=g_ctx,  B=g_outw -> C (fp32)
// MODE 1: A=g_x,    B=g_ipw  -> g_q/g_k/g_v fp16 hi/lo (q scaled)
// MODE 2: A=g_x,    B=g_relw -> g_vals fp32
// ---------------------------------------------------------------------------
#define RS 80                      // smem row stride bytes (32 fp16 + pad)
#define MATB (128*RS)              // 10240
#define STAGEB (4*MATB)            // 40960
#define SM_GEMM (2*STAGEB)         // 81920

template<int MODE>
__global__ __launch_bounds__(256, 2) void hgemm2(
    const float* __restrict__ bias, float* __restrict__ C,
    int M, int N, int K)
{
    extern __shared__ __align__(16) char smem[];
    const __half* Ah = (MODE == 0) ? g_ctx_h : g_x_h;
    const __half* Al = (MODE == 0) ? g_ctx_l : g_x_l;
    const __half* Bh = (MODE == 0) ? g_outw_h : (MODE == 1 ? g_ipw_h : g_relw_h);
    const __half* Bl = (MODE == 0) ? g_outw_l : (MODE == 1 ? g_ipw_l : g_relw_l);

    int tid = threadIdx.x, lane = tid & 31, wid = tid >> 5;
    int wm = wid & 1, wn = wid >> 1;
    int m0 = blockIdx.y * 128, n0 = blockIdx.x * 128;
    uint32_t sbase = smem_u32(smem);

    int rowA = (lane & 7) + ((lane >> 3) & 1) * 8;
    int colA = ((lane >> 4) & 1) * 16;
    int rowB = (lane & 7) + ((lane >> 4) & 1) * 8;
    int colB = ((lane >> 3) & 1) * 16;
    uint32_t offAh = (uint32_t)((wm*64 + rowA) * RS + colA);
    uint32_t offAl = offAh + MATB;
    uint32_t offBh = (uint32_t)(2*MATB + (wn*32 + rowB) * RS + colB);
    uint32_t offBl = offBh + MATB;

    const __half* srcs[4] = {Ah, Al, Bh, Bl};

    float acc[16][4];
#pragma unroll
    for (int i = 0; i < 16; i++) { acc[i][0]=acc[i][1]=acc[i][2]=acc[i][3]=0.f; }

    auto load_stage = [&](int stage, int k0) {
        uint32_t dstb = sbase + stage * STAGEB;
#pragma unroll
        for (int it = 0; it < 8; it++) {
            int c = tid + it * 256;                 // 2048 16B chunks
            int mat = c >> 9, r = (c >> 2) & 127, cc = c & 3;
            int grow = ((mat < 2) ? m0 : n0) + r;
            const __half* src = srcs[mat] + (size_t)grow * K + k0 + cc * 8;
            cp16(dstb + mat*MATB + r*RS + cc*16, src);
        }
        CP_COMMIT();
    };

    auto compute = [&](int stage) {
        uint32_t st = sbase + stage * STAGEB;
        uint32_t uAh = st + offAh, uAl = st + offAl;
        uint32_t uBh = st + offBh, uBl = st + offBl;
#pragma unroll
        for (int ks = 0; ks < 2; ks++) {
            uint32_t bh[4][2], bl[4][2];
#pragma unroll
            for (int np = 0; np < 2; np++) {
                uint32_t t[4];
                ldsm4(t, uBh + np*(16*RS) + ks*32);
                bh[2*np][0]=t[0]; bh[2*np][1]=t[1];
                bh[2*np+1][0]=t[2]; bh[2*np+1][1]=t[3];
                ldsm4(t, uBl + np*(16*RS) + ks*32);
                bl[2*np][0]=t[0]; bl[2*np][1]=t[1];
                bl[2*np+1][0]=t[2]; bl[2*np+1][1]=t[3];
            }
            uint32_t a[4][4];
#pragma unroll
            for (int mt = 0; mt < 4; mt++)
                ldsm4(a[mt], uAh + mt*(16*RS) + ks*32);
#pragma unroll
            for (int mt = 0; mt < 4; mt++)
#pragma unroll
                for (int nt = 0; nt < 4; nt++)
                    mma16816(acc[mt*4+nt], a[mt], bh[nt]);
#pragma unroll
            for (int mt = 0; mt < 4; mt++)
#pragma unroll
                for (int nt = 0; nt < 4; nt++)
                    mma16816(acc[mt*4+nt], a[mt], bl[nt]);
#pragma unroll
            for (int mt = 0; mt < 4; mt++)
                ldsm4(a[mt], uAl + mt*(16*RS) + ks*32);
#pragma unroll
            for (int mt = 0; mt < 4; mt++)
#pragma unroll
                for (int nt = 0; nt < 4; nt++)
                    mma16816(acc[mt*4+nt], a[mt], bh[nt]);
        }
    };

    const int nChunks = K >> 5;
    load_stage(0, 0);
    for (int c = 0; c < nChunks; c++) {
        if (c + 1 < nChunks) { load_stage((c + 1) & 1, (c + 1) * 32); CP_WAIT(1); }
        else                 { CP_WAIT(0); }
        __syncthreads();
        compute(c & 1);
        __syncthreads();
    }

    // ---- epilogue ----
#pragma unroll
    for (int mt = 0; mt < 4; mt++) {
#pragma unroll
        for (int nt = 0; nt < 4; nt++) {
            float* ac = acc[mt*4+nt];
            int nb = n0 + wn*32 + nt*8 + (lane & 3)*2;
            float bv0 = bias[nb], bv1 = bias[nb+1];
#pragma unroll
            for (int hh = 0; hh < 2; hh++) {
                int m = m0 + wm*64 + mt*16 + (lane >> 2) + hh*8;
                float v0 = ac[2*hh] + bv0, v1 = ac[2*hh+1] + bv1;
                if (MODE == 0) {
                    *(float2*)(C + (size_t)m * N + nb) = make_float2(v0, v1);
                } else if (MODE == 1) {
                    int tg = m >> 2, bb = m & 3;
                    int part = nb >> 10, e = nb & 1023;
                    int hd = e >> 6, dd = e & 63;
                    if (part == 0) { v0 *= 0.125f; v1 *= 0.125f; }
                    uint32_t hi, lo;
                    split2(v0, v1, hi, lo);
                    size_t off = ((size_t)(bb*Hn + hd) * TGTn + tg) * HDn + dd;
                    __half *dh, *dl;
                    if (part == 0)      { dh = g_q_h; dl = g_q_l; }
                    else if (part == 1) { dh = g_k_h; dl = g_k_l; }
                    else                { dh = g_v_h; dl = g_v_l; }
                    *(uint32_t*)(dh + off) = hi;
                    *(uint32_t*)(dl + off) = lo;
                } else {
                    int tg = m >> 2, bb = m & 3;
                    int nbk0 = nb >> 4, hc0 = nb & 15;
                    int nbk1 = (nb+1) >> 4, hc1 = (nb+1) & 15;
                    g_vals[(((size_t)bb*TGTn + tg)*Hn + hc0)*NBn + nbk0] = v0;
                    g_vals[(((size_t)bb*TGTn + tg)*Hn + hc1)*NBn + nbk1] = v1;
                }
            }
        }
    }
}

// ---------------------------------------------------------------------------
// HMMA flash attention. TM=128 q-rows x BS=64 keys, 256 threads (8 warps,
// each warp m16 x n64). grid = (4 qtiles, 64 bh, 3 variants).
// Ngram second-half (diag-only) handled as 2 extra diagonal-masked tiles.
// ---------------------------------------------------------------------------
#define ARS 144                       // attn smem row stride bytes (64 fp16 + pad)
#define O_QH 0
#define O_QL (128*ARS)                // 18432
#define O_KH (2*128*ARS)              // 36864
#define O_KL (O_KH + 64*ARS)          // 46080
#define O_VH (O_KL + 64*ARS)          // 55296
#define O_VL (O_VH + 64*ARS)          // 64512
#define O_VALS (O_VL + 64*ARS)        // 73728
#define SM_ATTN (O_VALS + 128*32*4)   // 90112

__global__ __launch_bounds__(256) void attn2(
    const int* __restrict__ main_buckets,   // (B,T,T)
    const int* __restrict__ pred_buckets)   // (B,T,2T)
{
    extern __shared__ __align__(16) char smem[];
    float* sVals = (float*)(smem + O_VALS);
    uint32_t sbase = smem_u32(smem);

    int tid = threadIdx.x, lane = tid & 31, w = tid >> 5;
    int tileX = blockIdx.x;              // 0..3 (128 q rows each)
    int bh = blockIdx.y;                 // 0..63
    int var = blockIdx.z;                // 0 main, 1..2 ngram
    int b = bh >> 4, h = bh & 15;
    int qoff = (var == 0) ? 0 : (Tn + (var - 1) * Tn);
    int t0 = tileX * 128;

    // ---- load Q (hi/lo) + sVals ----
#pragma unroll
    for (int it = 0; it < 8; it++) {
        int s = tid + it * 256;                 // 2048 uint4 slots
        int buf = s >> 10, r = (s >> 3) & 127, cc = s & 7;
        const __half* src = (buf ? g_q_l : g_q_h)
            + ((size_t)bh * TGTn + qoff + t0 + r) * HDn + cc * 8;
        *(uint4*)(smem + (buf ? O_QL : O_QH) + r*ARS + cc*16) = *(const uint4*)src;
    }
#pragma unroll
    for (int it = 0; it < 4; it++) {
        int s = tid + it * 256;                 // 1024 float4 slots
        int r = s >> 3, cc = s & 7;
        const float* src = g_vals
            + (((size_t)b * TGTn + qoff + t0 + r) * Hn + h) * NBn + cc * 4;
        *(float4*)(sVals + r*32 + cc*4) = *(const float4*)src;
    }

    // ldmatrix lane addressing
    int rowA = (lane & 7) + ((lane >> 3) & 1) * 8;
    int colA = ((lane >> 4) & 1) * 16;
    int rowB = (lane & 7) + ((lane >> 4) & 1) * 8;
    int colB = ((lane >> 3) & 1) * 16;
    int rowV = (lane & 7) + ((lane >> 3) & 1) * 8;     // trans
    int colV = ((lane >> 4) & 1) * 16;
    uint32_t aQh = sbase + O_QH + (uint32_t)((16*w + rowA)*ARS + colA);
    uint32_t aQl = aQh + (uint32_t)(O_QL - O_QH);
    uint32_t aKh = sbase + O_KH + (uint32_t)(rowB*ARS + colB);
    uint32_t aKl = sbase + O_KL + (uint32_t)(rowB*ARS + colB);
    uint32_t aVh = sbase + O_VH + (uint32_t)(rowV*ARS + colV);
    uint32_t aVl = sbase + O_VL + (uint32_t)(rowV*ARS + colV);

    const int* bbase;
    int bstr;
    if (var == 0) { bbase = main_buckets + (size_t)b * Tn * Tn;      bstr = Tn;   }
    else          { bbase = pred_buckets + (size_t)b * Tn * 2 * Tn;  bstr = 2*Tn; }

    float m_[2] = {-1e30f, -1e30f}, l_[2] = {0.f, 0.f};
    float o[8][4];
#pragma unroll
    for (int j = 0; j < 8; j++) { o[j][0]=o[j][1]=o[j][2]=o[j][3]=0.f; }

    const __half* gkv[4] = {g_k_h, g_k_l, g_v_h, g_v_l};
    const uint32_t dkv[4] = {O_KH, O_KL, O_VH, O_VL};

    int qrow0 = (lane >> 2);          // local row within warp tile (+8 for hh=1)
    int nTiles = 2*tileX + 2;
    int totTiles = nTiles + ((var != 0) ? 2 : 0);

    for (int st = 0; st < totTiles; st++) {
        bool extra = (st >= nTiles);
        int e = st - nTiles;                       // 0/1 for extra
        int s0 = st * 64;
        int krow0 = extra ? (qoff + t0 + 64*e) : s0;

        __syncthreads();
#pragma unroll
        for (int it = 0; it < 8; it++) {
            int s = tid + it * 256;                // 2048 uint4 slots
            int buf = s >> 9, r = (s >> 3) & 63, cc = s & 7;
            const __half* src = gkv[buf]
                + ((size_t)bh * TGTn + krow0 + r) * HDn + cc * 8;
            *(uint4*)(smem + dkv[buf] + r*ARS + cc*16) = *(const uint4*)src;
        }
        __syncthreads();

        // ---- scores: S = Q K^T (3-pass split) ----
        float sc[8][4];
#pragma unroll
        for (int j = 0; j < 8; j++) { sc[j][0]=sc[j][1]=sc[j][2]=sc[j][3]=0.f; }
#pragma unroll
        for (int kk = 0; kk < 4; kk++) {
            uint32_t qh4[4], ql4[4];
            ldsm4(qh4, aQh + kk*32);
            ldsm4(ql4, aQl + kk*32);
#pragma unroll
            for (int np = 0; np < 4; np++) {
                uint32_t th[4], tl[4];
                ldsm4(th, aKh + np*(16*ARS) + kk*32);
                ldsm4(tl, aKl + np*(16*ARS) + kk*32);
                mma16816(sc[2*np],   qh4, th);
                mma16816(sc[2*np+1], qh4, th+2);
                mma16816(sc[2*np],   ql4, th);
                mma16816(sc[2*np+1], ql4, th+2);
                mma16816(sc[2*np],   qh4, tl);
                mma16816(sc[2*np+1], qh4, tl+2);
            }
        }

        // ---- bias gather + mask ----
#pragma unroll
        for (int j = 0; j < 8; j++) {
            int coll = 8*j + (lane & 3)*2;
#pragma unroll
            for (int hh = 0; hh < 2; hh++) {
                int qr = 16*w + qrow0 + 8*hh;              // 0..127
                int bcol = extra ? (Tn + t0 + 64*e + coll) : (s0 + coll);
                int2 bk = *(const int2*)(bbase + (size_t)(t0 + qr) * bstr + bcol);
                bool v0, v1;
                if (extra) { v0 = (qr == 64*e + coll); v1 = (qr == 64*e + coll + 1); }
                else       { v0 = (s0 + coll) <= (t0 + qr); v1 = (s0 + coll + 1) <= (t0 + qr); }
                sc[j][2*hh]   = v0 ? (sc[j][2*hh]   + sVals[qr*32 + bk.x]) : -1e30f;
                sc[j][2*hh+1] = v1 ? (sc[j][2*hh+1] + sVals[qr*32 + bk.y]) : -1e30f;
            }
        }

        // ---- online softmax ----
#pragma unroll
        for (int hh = 0; hh < 2; hh++) {
            float rm = -1e30f;
#pragma unroll
            for (int j = 0; j < 8; j++)
                rm = fmaxf(rm, fmaxf(sc[j][2*hh], sc[j][2*hh+1]));
            rm = fmaxf(rm, __shfl_xor_sync(0xffffffffu, rm, 1));
            rm = fmaxf(rm, __shfl_xor_sync(0xffffffffu, rm, 2));
            float mnew = fmaxf(m_[hh], rm);
            float scale = __expf(m_[hh] - mnew);
            float sum = 0.f;
#pragma unroll
            for (int j = 0; j < 8; j++) {
                float p0 = __expf(sc[j][2*hh]   - mnew);
                float p1 = __expf(sc[j][2*hh+1] - mnew);
                sc[j][2*hh] = p0; sc[j][2*hh+1] = p1;
                sum += p0 + p1;
            }
            sum += __shfl_xor_sync(0xffffffffu, sum, 1);
            sum += __shfl_xor_sync(0xffffffffu, sum, 2);
            l_[hh] = l_[hh] * scale + sum;
            m_[hh] = mnew;
#pragma unroll
            for (int j = 0; j < 8; j++) {
                o[j][2*hh]   *= scale;
                o[j][2*hh+1] *= scale;
            }
        }

        // ---- O += P V (3-pass split; P frags straight from registers) ----
#pragma unroll
        for (int kk2 = 0; kk2 < 4; kk2++) {
            uint32_t ahi[4], alo[4];
            split2(sc[2*kk2][0],   sc[2*kk2][1],   ahi[0], alo[0]);
            split2(sc[2*kk2][2],   sc[2*kk2][3],   ahi[1], alo[1]);
            split2(sc[2*kk2+1][0], sc[2*kk2+1][1], ahi[2], alo[2]);
            split2(sc[2*kk2+1][2], sc[2*kk2+1][3], ahi[3], alo[3]);
#pragma unroll
            for (int ng = 0; ng < 4; ng++) {
                uint32_t vh4[4], vl4[4];
                ldsm4t(vh4, aVh + kk2*(16*ARS) + ng*32);
                ldsm4t(vl4, aVl + kk2*(16*ARS) + ng*32);
                mma16816(o[2*ng],   ahi, vh4);
                mma16816(o[2*ng+1], ahi, vh4+2);
                mma16816(o[2*ng],   alo, vh4);
                mma16816(o[2*ng+1], alo, vh4+2);
                mma16816(o[2*ng],   ahi, vl4);
                mma16816(o[2*ng+1], ahi, vl4+2);
            }
        }
    }

    // ---- epilogue: ctx (fp16 hi/lo) = O / l ----
#pragma unroll
    for (int hh = 0; hh < 2; hh++) {
        int qr = 16*w + qrow0 + 8*hh;
        int tg = qoff + t0 + qr;
        float inv = 1.0f / l_[hh];
#pragma unroll
        for (int j = 0; j < 8; j++) {
            int col = 8*j + (lane & 3)*2;
            float x0 = o[j][2*hh] * inv, x1 = o[j][2*hh+1] * inv;
            uint32_t hi, lo;
            split2(x0, x1, hi, lo);
            size_t off = ((size_t)tg * Bn + b) * En + h * HDn + col;
            *(uint32_t*)(g_ctx_h + off) = hi;
            *(uint32_t*)(g_ctx_l + off) = lo;
        }
    }
}

// ---------------------------------------------------------------------------
extern "C" void kernel_launch(void* const* d_in, const int* in_sizes, int n_in,
                              void* d_out, int out_size) {
    const float* query = (const float*)d_in[0];
    const float* ipw   = (const float*)d_in[1];
    const float* ipb   = (const float*)d_in[2];
    const float* relw  = (const float*)d_in[3];
    const float* relb  = (const float*)d_in[4];
    const float* outw  = (const float*)d_in[5];
    const float* outb  = (const float*)d_in[6];
    const int*   mb    = (const int*)d_in[7];
    const int*   pb    = (const int*)d_in[8];
    float* out = (float*)d_out;

    cudaFuncSetAttribute(hgemm2<0>, cudaFuncAttributeMaxDynamicSharedMemorySize, SM_GEMM);
    cudaFuncSetAttribute(hgemm2<1>, cudaFuncAttributeMaxDynamicSharedMemorySize, SM_GEMM);
    cudaFuncSetAttribute(hgemm2<2>, cudaFuncAttributeMaxDynamicSharedMemorySize, SM_GEMM);
    cudaFuncSetAttribute(attn2,     cudaFuncAttributeMaxDynamicSharedMemorySize, SM_ATTN);

    // 0) pre-convert operands to fp16 hi/lo
    convert_kernel<<<Mrows*En/1024, 256>>>(query, Mrows*En, 0);
    convert_kernel<<<3*En*En/1024, 256>>>(ipw, 3*En*En, 1);
    convert_kernel<<<NBn*Hn*En/1024, 256>>>(relw, NBn*Hn*En, 2);
    convert_kernel<<<En*En/1024, 256>>>(outw, En*En, 3);

    // 1) qkv projection (scatter fp16 hi/lo head layout, q scaled)
    hgemm2<1><<<dim3(24, 48), 256, SM_GEMM>>>(ipb, nullptr, Mrows, 3*En, En);
    // 2) rel-bucket value table (fp32)
    hgemm2<2><<<dim3(4, 48), 256, SM_GEMM>>>(relb, nullptr, Mrows, NBn*Hn, En);
    // 3) fused HMMA flash attention
    attn2<<<dim3(4, 64, 3), 256, SM_ATTN>>>(mb, pb);
    // 4) output projection -> d_out
    hgemm2<0><<<dim3(8, 48), 256, SM_GEMM>>>(outb, out, Mrows, En, En);
}

// round 9
// speedup vs baseline: 4.5691x; 1.0882x over previous
#include <cuda_runtime.h>
#include <cuda_fp16.h>
#include <cstdint>

#define Tn    512
#define Bn    4
#define En    1024
#define Hn    16
#define HDn   64
#define NBn   32
#define TGTn  1536
#define BHn   64
#define Mrows (TGTn*Bn)   /* 6144 */

// -------- scratch (static device globals) --------
__device__ __half g_x_h[(size_t)Mrows*En],    g_x_l[(size_t)Mrows*En];
__device__ __half g_ipw_h[(size_t)3*En*En],   g_ipw_l[(size_t)3*En*En];
__device__ __half g_relw_h[(size_t)NBn*Hn*En],g_relw_l[(size_t)NBn*Hn*En];
__device__ __half g_outw_h[(size_t)En*En],    g_outw_l[(size_t)En*En];
__device__ __half g_ctx_h[(size_t)Mrows*En],  g_ctx_l[(size_t)Mrows*En];
__device__ __half g_q_h[(size_t)BHn*TGTn*HDn], g_q_l[(size_t)BHn*TGTn*HDn];
__device__ __half g_k_h[(size_t)BHn*TGTn*HDn], g_k_l[(size_t)BHn*TGTn*HDn];
__device__ __half g_v_h[(size_t)BHn*TGTn*HDn], g_v_l[(size_t)BHn*TGTn*HDn];
__device__ float  g_vals[(size_t)Bn*TGTn*Hn*NBn];   // [b][tg][h][nb]

// ============================ helpers ==================================
__device__ __forceinline__ uint32_t smem_u32(const void* p) {
    uint32_t a;
    asm("{ .reg .u64 t; cvta.to.shared.u64 t, %1; cvt.u32.u64 %0, t; }"
        : "=r"(a) : "l"(p));
    return a;
}
__device__ __forceinline__ void ldsm4(uint32_t* r, uint32_t addr) {
    asm volatile("ldmatrix.sync.aligned.m8n8.x4.shared.b16 {%0,%1,%2,%3}, [%4];"
                 : "=r"(r[0]), "=r"(r[1]), "=r"(r[2]), "=r"(r[3]) : "r"(addr));
}
__device__ __forceinline__ void ldsm4t(uint32_t* r, uint32_t addr) {
    asm volatile("ldmatrix.sync.aligned.m8n8.x4.trans.shared.b16 {%0,%1,%2,%3}, [%4];"
                 : "=r"(r[0]), "=r"(r[1]), "=r"(r[2]), "=r"(r[3]) : "r"(addr));
}
__device__ __forceinline__ void mma16816(float* c, const uint32_t* a, const uint32_t* b) {
    asm volatile(
        "mma.sync.aligned.m16n8k16.row.col.f32.f16.f16.f32 "
        "{%0,%1,%2,%3}, {%4,%5,%6,%7}, {%8,%9}, {%0,%1,%2,%3};"
        : "+f"(c[0]), "+f"(c[1]), "+f"(c[2]), "+f"(c[3])
        : "r"(a[0]), "r"(a[1]), "r"(a[2]), "r"(a[3]), "r"(b[0]), "r"(b[1]));
}
__device__ __forceinline__ void cp16(uint32_t dst, const void* src) {
    asm volatile("cp.async.cg.shared.global [%0], [%1], 16;"
                 :: "r"(dst), "l"(src) : "memory");
}
#define CP_COMMIT() asm volatile("cp.async.commit_group;" ::: "memory")
#define CP_WAIT(N)  asm volatile("cp.async.wait_group %0;" :: "n"(N) : "memory")

__device__ __forceinline__ void split2(float x, float y, uint32_t& hi, uint32_t& lo) {
    __half hx = __float2half_rn(x), hy = __float2half_rn(y);
    __half lx = __float2half_rn(x - __half2float(hx));
    __half ly = __float2half_rn(y - __half2float(hy));
    __half2 h = __halves2half2(hx, hy), l = __halves2half2(lx, ly);
    hi = *(uint32_t*)&h; lo = *(uint32_t*)&l;
}
__device__ __forceinline__ float2 h2sum(uint32_t h, uint32_t l) {
    float2 a = __half22float2(*(__half2*)&h);
    float2 b = __half22float2(*(__half2*)&l);
    return make_float2(a.x + b.x, a.y + b.y);
}

// ---------------------------------------------------------------------------
// Fused pre-convert: f32 -> fp16 hi/lo for all four operand tensors.
// Segment map (in 1024-element blocks): [0,6144)=x, [6144,9216)=ipw,
// [9216,9728)=relw, [9728,10752)=outw.
// ---------------------------------------------------------------------------
__global__ __launch_bounds__(256) void convert_all(
    const float* __restrict__ q, const float* __restrict__ w1,
    const float* __restrict__ w2, const float* __restrict__ w3)
{
    int bid = blockIdx.x;
    const float* src; __half *dh, *dl; int lb;
    if (bid < 6144)      { src = q;  dh = g_x_h;    dl = g_x_l;    lb = bid; }
    else if (bid < 9216) { src = w1; dh = g_ipw_h;  dl = g_ipw_l;  lb = bid - 6144; }
    else if (bid < 9728) { src = w2; dh = g_relw_h; dl = g_relw_l; lb = bid - 9216; }
    else                 { src = w3; dh = g_outw_h; dl = g_outw_l; lb = bid - 9728; }
    int i = (lb * 256 + threadIdx.x) * 4;
    float4 v = *(const float4*)(src + i);
    uint32_t h01, l01, h23, l23;
    split2(v.x, v.y, h01, l01);
    split2(v.z, v.w, h23, l23);
    *(uint2*)(dh + i) = make_uint2(h01, h23);
    *(uint2*)(dl + i) = make_uint2(l01, l23);
}

// ---------------------------------------------------------------------------
// HMMA GEMM (fp16 split 3-pass, cp.async 2-stage): C = A*B^T + bias
// (unchanged from Round 6)
// ---------------------------------------------------------------------------
#define RS 80
#define MATB (128*RS)
#define STAGEB (4*MATB)
#define SM_GEMM (2*STAGEB)

template<int MODE>
__global__ __launch_bounds__(256, 2) void hgemm2(
    const float* __restrict__ bias, float* __restrict__ C,
    int M, int N, int K)
{
    extern __shared__ __align__(16) char smem[];
    const __half* Ah = (MODE == 0) ? g_ctx_h : g_x_h;
    const __half* Al = (MODE == 0) ? g_ctx_l : g_x_l;
    const __half* Bh = (MODE == 0) ? g_outw_h : (MODE == 1 ? g_ipw_h : g_relw_h);
    const __half* Bl = (MODE == 0) ? g_outw_l : (MODE == 1 ? g_ipw_l : g_relw_l);

    int tid = threadIdx.x, lane = tid & 31, wid = tid >> 5;
    int wm = wid & 1, wn = wid >> 1;
    int m0 = blockIdx.y * 128, n0 = blockIdx.x * 128;
    uint32_t sbase = smem_u32(smem);

    int rowA = (lane & 7) + ((lane >> 3) & 1) * 8;
    int colA = ((lane >> 4) & 1) * 16;
    int rowB = (lane & 7) + ((lane >> 4) & 1) * 8;
    int colB = ((lane >> 3) & 1) * 16;
    uint32_t offAh = (uint32_t)((wm*64 + rowA) * RS + colA);
    uint32_t offAl = offAh + MATB;
    uint32_t offBh = (uint32_t)(2*MATB + (wn*32 + rowB) * RS + colB);
    uint32_t offBl = offBh + MATB;

    const __half* srcs[4] = {Ah, Al, Bh, Bl};

    float acc[16][4];
#pragma unroll
    for (int i = 0; i < 16; i++) { acc[i][0]=acc[i][1]=acc[i][2]=acc[i][3]=0.f; }

    auto load_stage = [&](int stage, int k0) {
        uint32_t dstb = sbase + stage * STAGEB;
#pragma unroll
        for (int it = 0; it < 8; it++) {
            int c = tid + it * 256;
            int mat = c >> 9, r = (c >> 2) & 127, cc = c & 3;
            int grow = ((mat < 2) ? m0 : n0) + r;
            const __half* src = srcs[mat] + (size_t)grow * K + k0 + cc * 8;
            cp16(dstb + mat*MATB + r*RS + cc*16, src);
        }
        CP_COMMIT();
    };

    auto compute = [&](int stage) {
        uint32_t st = sbase + stage * STAGEB;
        uint32_t uAh = st + offAh, uAl = st + offAl;
        uint32_t uBh = st + offBh, uBl = st + offBl;
#pragma unroll
        for (int ks = 0; ks < 2; ks++) {
            uint32_t bh[4][2], bl[4][2];
#pragma unroll
            for (int np = 0; np < 2; np++) {
                uint32_t t[4];
                ldsm4(t, uBh + np*(16*RS) + ks*32);
                bh[2*np][0]=t[0]; bh[2*np][1]=t[1];
                bh[2*np+1][0]=t[2]; bh[2*np+1][1]=t[3];
                ldsm4(t, uBl + np*(16*RS) + ks*32);
                bl[2*np][0]=t[0]; bl[2*np][1]=t[1];
                bl[2*np+1][0]=t[2]; bl[2*np+1][1]=t[3];
            }
            uint32_t a[4][4];
#pragma unroll
            for (int mt = 0; mt < 4; mt++)
                ldsm4(a[mt], uAh + mt*(16*RS) + ks*32);
#pragma unroll
            for (int mt = 0; mt < 4; mt++)
#pragma unroll
                for (int nt = 0; nt < 4; nt++)
                    mma16816(acc[mt*4+nt], a[mt], bh[nt]);
#pragma unroll
            for (int mt = 0; mt < 4; mt++)
#pragma unroll
                for (int nt = 0; nt < 4; nt++)
                    mma16816(acc[mt*4+nt], a[mt], bl[nt]);
#pragma unroll
            for (int mt = 0; mt < 4; mt++)
                ldsm4(a[mt], uAl + mt*(16*RS) + ks*32);
#pragma unroll
            for (int mt = 0; mt < 4; mt++)
#pragma unroll
                for (int nt = 0; nt < 4; nt++)
                    mma16816(acc[mt*4+nt], a[mt], bh[nt]);
        }
    };

    const int nChunks = K >> 5;
    load_stage(0, 0);
    for (int c = 0; c < nChunks; c++) {
        if (c + 1 < nChunks) { load_stage((c + 1) & 1, (c + 1) * 32); CP_WAIT(1); }
        else                 { CP_WAIT(0); }
        __syncthreads();
        compute(c & 1);
        __syncthreads();
    }

#pragma unroll
    for (int mt = 0; mt < 4; mt++) {
#pragma unroll
        for (int nt = 0; nt < 4; nt++) {
            float* ac = acc[mt*4+nt];
            int nb = n0 + wn*32 + nt*8 + (lane & 3)*2;
            float bv0 = bias[nb], bv1 = bias[nb+1];
#pragma unroll
            for (int hh = 0; hh < 2; hh++) {
                int m = m0 + wm*64 + mt*16 + (lane >> 2) + hh*8;
                float v0 = ac[2*hh] + bv0, v1 = ac[2*hh+1] + bv1;
                if (MODE == 0) {
                    *(float2*)(C + (size_t)m * N + nb) = make_float2(v0, v1);
                } else if (MODE == 1) {
                    int tg = m >> 2, bb = m & 3;
                    int part = nb >> 10, e = nb & 1023;
                    int hd = e >> 6, dd = e & 63;
                    if (part == 0) { v0 *= 0.125f; v1 *= 0.125f; }
                    uint32_t hi, lo;
                    split2(v0, v1, hi, lo);
                    size_t off = ((size_t)(bb*Hn + hd) * TGTn + tg) * HDn + dd;
                    __half *dh, *dl;
                    if (part == 0)      { dh = g_q_h; dl = g_q_l; }
                    else if (part == 1) { dh = g_k_h; dl = g_k_l; }
                    else                { dh = g_v_h; dl = g_v_l; }
                    *(uint32_t*)(dh + off) = hi;
                    *(uint32_t*)(dl + off) = lo;
                } else {
                    int tg = m >> 2, bb = m & 3;
                    int nbk0 = nb >> 4, hc0 = nb & 15;
                    int nbk1 = (nb+1) >> 4, hc1 = (nb+1) & 15;
                    g_vals[(((size_t)bb*TGTn + tg)*Hn + hc0)*NBn + nbk0] = v0;
                    g_vals[(((size_t)bb*TGTn + tg)*Hn + hc1)*NBn + nbk1] = v1;
                }
            }
        }
    }
}

// ---------------------------------------------------------------------------
// HMMA flash attention v3: causal tiles only, warp-uniform beyond-diagonal
// skip, ngram diagonal handled as a SIMT scalar merge (no extra tiles).
// TM=128 x BS=64, 256 threads (8 warps, m16 x n64 each).
// ---------------------------------------------------------------------------
#define ARS 144
#define O_QH 0
#define O_QL (128*ARS)
#define O_KH (2*128*ARS)
#define O_KL (O_KH + 64*ARS)
#define O_VH (O_KL + 64*ARS)
#define O_VL (O_VH + 64*ARS)
#define O_VALS (O_VL + 64*ARS)
#define SM_ATTN (O_VALS + 128*32*4)   // 90112

__global__ __launch_bounds__(256) void attn2(
    const int* __restrict__ main_buckets,
    const int* __restrict__ pred_buckets)
{
    extern __shared__ __align__(16) char smem[];
    float* sVals = (float*)(smem + O_VALS);
    uint32_t sbase = smem_u32(smem);

    int tid = threadIdx.x, lane = tid & 31, w = tid >> 5;
    int tileX = blockIdx.x;              // 0..3
    int bh = blockIdx.y;                 // 0..63
    int var = blockIdx.z;                // 0 main, 1..2 ngram
    int b = bh >> 4, h = bh & 15;
    int qoff = (var == 0) ? 0 : (Tn + (var - 1) * Tn);
    int t0 = tileX * 128;

    // ---- load Q (hi/lo) + sVals ----
#pragma unroll
    for (int it = 0; it < 8; it++) {
        int s = tid + it * 256;
        int buf = s >> 10, r = (s >> 3) & 127, cc = s & 7;
        const __half* src = (buf ? g_q_l : g_q_h)
            + ((size_t)bh * TGTn + qoff + t0 + r) * HDn + cc * 8;
        *(uint4*)(smem + (buf ? O_QL : O_QH) + r*ARS + cc*16) = *(const uint4*)src;
    }
#pragma unroll
    for (int it = 0; it < 4; it++) {
        int s = tid + it * 256;
        int r = s >> 3, cc = s & 7;
        const float* src = g_vals
            + (((size_t)b * TGTn + qoff + t0 + r) * Hn + h) * NBn + cc * 4;
        *(float4*)(sVals + r*32 + cc*4) = *(const float4*)src;
    }

    int rowA = (lane & 7) + ((lane >> 3) & 1) * 8;
    int colA = ((lane >> 4) & 1) * 16;
    int rowB = (lane & 7) + ((lane >> 4) & 1) * 8;
    int colB = ((lane >> 3) & 1) * 16;
    int rowV = (lane & 7) + ((lane >> 3) & 1) * 8;
    int colV = ((lane >> 4) & 1) * 16;
    uint32_t aQh = sbase + O_QH + (uint32_t)((16*w + rowA)*ARS + colA);
    uint32_t aQl = aQh + (uint32_t)(O_QL - O_QH);
    uint32_t aKh = sbase + O_KH + (uint32_t)(rowB*ARS + colB);
    uint32_t aKl = sbase + O_KL + (uint32_t)(rowB*ARS + colB);
    uint32_t aVh = sbase + O_VH + (uint32_t)(rowV*ARS + colV);
    uint32_t aVl = sbase + O_VL + (uint32_t)(rowV*ARS + colV);

    const int* bbase;
    int bstr;
    if (var == 0) { bbase = main_buckets + (size_t)b * Tn * Tn;      bstr = Tn;   }
    else          { bbase = pred_buckets + (size_t)b * Tn * 2 * Tn;  bstr = 2*Tn; }

    float m_[2] = {-1e30f, -1e30f}, l_[2] = {0.f, 0.f};
    float o[8][4];
#pragma unroll
    for (int j = 0; j < 8; j++) { o[j][0]=o[j][1]=o[j][2]=o[j][3]=0.f; }

    const __half* gkv[4] = {g_k_h, g_k_l, g_v_h, g_v_l};
    const uint32_t dkv[4] = {O_KH, O_KL, O_VH, O_VL};

    int qrow0 = (lane >> 2);
    int lim = t0 + 16*w + 15;            // max absolute q row for this warp
    int nTiles = 2*tileX + 2;            // causal tiles only

    for (int st = 0; st < nTiles; st++) {
        int s0 = st * 64;

        __syncthreads();
#pragma unroll
        for (int it = 0; it < 8; it++) {
            int s = tid + it * 256;
            int buf = s >> 9, r = (s >> 3) & 63, cc = s & 7;
            const __half* src = gkv[buf]
                + ((size_t)bh * TGTn + s0 + r) * HDn + cc * 8;
            *(uint4*)(smem + dkv[buf] + r*ARS + cc*16) = *(const uint4*)src;
        }
        __syncthreads();

        if (s0 > lim) continue;          // whole tile beyond diagonal for warp

        bool jskip[8];
#pragma unroll
        for (int j = 0; j < 8; j++) jskip[j] = (s0 + 8*j > lim);

        // ---- scores ----
        float sc[8][4];
#pragma unroll
        for (int j = 0; j < 8; j++) { sc[j][0]=sc[j][1]=sc[j][2]=sc[j][3]=0.f; }
#pragma unroll
        for (int kk = 0; kk < 4; kk++) {
            uint32_t qh4[4], ql4[4];
            ldsm4(qh4, aQh + kk*32);
            ldsm4(ql4, aQl + kk*32);
#pragma unroll
            for (int np = 0; np < 4; np++) {
                if (jskip[2*np]) continue;    // both halves masked (warp-uniform)
                uint32_t th[4], tl[4];
                ldsm4(th, aKh + np*(16*ARS) + kk*32);
                ldsm4(tl, aKl + np*(16*ARS) + kk*32);
                mma16816(sc[2*np],   qh4, th);
                mma16816(sc[2*np+1], qh4, th+2);
                mma16816(sc[2*np],   ql4, th);
                mma16816(sc[2*np+1], ql4, th+2);
                mma16816(sc[2*np],   qh4, tl);
                mma16816(sc[2*np+1], qh4, tl+2);
            }
        }

        // ---- bias gather + causal mask ----
#pragma unroll
        for (int j = 0; j < 8; j++) {
            if (jskip[j]) continue;
            int coll = 8*j + (lane & 3)*2;
#pragma unroll
            for (int hh = 0; hh < 2; hh++) {
                int qr = 16*w + qrow0 + 8*hh;
                int2 bk = *(const int2*)(bbase + (size_t)(t0 + qr) * bstr + s0 + coll);
                bool v0 = (s0 + coll)     <= (t0 + qr);
                bool v1 = (s0 + coll + 1) <= (t0 + qr);
                sc[j][2*hh]   = v0 ? (sc[j][2*hh]   + sVals[qr*32 + bk.x]) : -1e30f;
                sc[j][2*hh+1] = v1 ? (sc[j][2*hh+1] + sVals[qr*32 + bk.y]) : -1e30f;
            }
        }

        // ---- online softmax (skip masked groups) ----
#pragma unroll
        for (int hh = 0; hh < 2; hh++) {
            float rm = -1e30f;
#pragma unroll
            for (int j = 0; j < 8; j++)
                if (!jskip[j]) rm = fmaxf(rm, fmaxf(sc[j][2*hh], sc[j][2*hh+1]));
            rm = fmaxf(rm, __shfl_xor_sync(0xffffffffu, rm, 1));
            rm = fmaxf(rm, __shfl_xor_sync(0xffffffffu, rm, 2));
            float mnew = fmaxf(m_[hh], rm);
            float scale = __expf(m_[hh] - mnew);
            float sum = 0.f;
#pragma unroll
            for (int j = 0; j < 8; j++) {
                if (jskip[j]) { sc[j][2*hh] = 0.f; sc[j][2*hh+1] = 0.f; continue; }
                float p0 = __expf(sc[j][2*hh]   - mnew);
                float p1 = __expf(sc[j][2*hh+1] - mnew);
                sc[j][2*hh] = p0; sc[j][2*hh+1] = p1;
                sum += p0 + p1;
            }
            sum += __shfl_xor_sync(0xffffffffu, sum, 1);
            sum += __shfl_xor_sync(0xffffffffu, sum, 2);
            l_[hh] = l_[hh] * scale + sum;
            m_[hh] = mnew;
#pragma unroll
            for (int j = 0; j < 8; j++) {
                o[j][2*hh]   *= scale;
                o[j][2*hh+1] *= scale;
            }
        }

        // ---- O += P V ----
#pragma unroll
        for (int kk2 = 0; kk2 < 4; kk2++) {
            if (jskip[2*kk2]) continue;       // P group all-zero (warp-uniform)
            uint32_t ahi[4], alo[4];
            split2(sc[2*kk2][0],   sc[2*kk2][1],   ahi[0], alo[0]);
            split2(sc[2*kk2][2],   sc[2*kk2][3],   ahi[1], alo[1]);
            split2(sc[2*kk2+1][0], sc[2*kk2+1][1], ahi[2], alo[2]);
            split2(sc[2*kk2+1][2], sc[2*kk2+1][3], ahi[3], alo[3]);
#pragma unroll
            for (int ng = 0; ng < 4; ng++) {
                uint32_t vh4[4], vl4[4];
                ldsm4t(vh4, aVh + kk2*(16*ARS) + ng*32);
                ldsm4t(vl4, aVl + kk2*(16*ARS) + ng*32);
                mma16816(o[2*ng],   ahi, vh4);
                mma16816(o[2*ng+1], ahi, vh4+2);
                mma16816(o[2*ng],   alo, vh4);
                mma16816(o[2*ng+1], alo, vh4+2);
                mma16816(o[2*ng],   ahi, vl4);
                mma16816(o[2*ng+1], ahi, vl4+2);
            }
        }
    }

    // ---- ngram diagonal key: SIMT scalar merge ----
    if (var != 0) {
#pragma unroll
        for (int hh = 0; hh < 2; hh++) {
            int qr = 16*w + qrow0 + 8*hh;
            int t = t0 + qr;
            size_t rowoff = ((size_t)bh * TGTn + qoff + t) * HDn;
            size_t doff = rowoff + (lane & 3) * 16;
            float dot = 0.f;
#pragma unroll
            for (int u = 0; u < 2; u++) {
                uint4 qh4 = *(const uint4*)(g_q_h + doff + u*8);
                uint4 ql4 = *(const uint4*)(g_q_l + doff + u*8);
                uint4 kh4 = *(const uint4*)(g_k_h + doff + u*8);
                uint4 kl4 = *(const uint4*)(g_k_l + doff + u*8);
                const uint32_t* qh_ = &qh4.x; const uint32_t* ql_ = &ql4.x;
                const uint32_t* kh_ = &kh4.x; const uint32_t* kl_ = &kl4.x;
#pragma unroll
                for (int c = 0; c < 4; c++) {
                    float2 qv = h2sum(qh_[c], ql_[c]);
                    float2 kv = h2sum(kh_[c], kl_[c]);
                    dot += qv.x*kv.x + qv.y*kv.y;
                }
            }
            dot += __shfl_xor_sync(0xffffffffu, dot, 1);
            dot += __shfl_xor_sync(0xffffffffu, dot, 2);
            int bkt = bbase[(size_t)t * bstr + Tn + t];
            float sd = dot + sVals[qr*32 + bkt];

            float mnew = fmaxf(m_[hh], sd);
            float scale = __expf(m_[hh] - mnew);
            float pd = __expf(sd - mnew);
            l_[hh] = l_[hh] * scale + pd;
            m_[hh] = mnew;
#pragma unroll
            for (int j = 0; j < 8; j++) {
                int col = 8*j + (lane & 3)*2;
                uint32_t vh = *(const uint32_t*)(g_v_h + rowoff + col);
                uint32_t vl = *(const uint32_t*)(g_v_l + rowoff + col);
                float2 vv = h2sum(vh, vl);
                o[j][2*hh]   = o[j][2*hh]   * scale + pd * vv.x;
                o[j][2*hh+1] = o[j][2*hh+1] * scale + pd * vv.y;
            }
        }
    }

    // ---- epilogue: ctx (fp16 hi/lo) = O / l ----
#pragma unroll
    for (int hh = 0; hh < 2; hh++) {
        int qr = 16*w + qrow0 + 8*hh;
        int tg = qoff + t0 + qr;
        float inv = 1.0f / l_[hh];
#pragma unroll
        for (int j = 0; j < 8; j++) {
            int col = 8*j + (lane & 3)*2;
            float x0 = o[j][2*hh] * inv, x1 = o[j][2*hh+1] * inv;
            uint32_t hi, lo;
            split2(x0, x1, hi, lo);
            size_t off = ((size_t)tg * Bn + b) * En + h * HDn + col;
            *(uint32_t*)(g_ctx_h + off) = hi;
            *(uint32_t*)(g_ctx_l + off) = lo;
        }
    }
}

// ---------------------------------------------------------------------------
extern "C" void kernel_launch(void* const* d_in, const int* in_sizes, int n_in,
                              void* d_out, int out_size) {
    const float* query = (const float*)d_in[0];
    const float* ipw   = (const float*)d_in[1];
    const float* ipb   = (const float*)d_in[2];
    const float* relw  = (const float*)d_in[3];
    const float* relb  = (const float*)d_in[4];
    const float* outw  = (const float*)d_in[5];
    const float* outb  = (const float*)d_in[6];
    const int*   mb    = (const int*)d_in[7];
    const int*   pb    = (const int*)d_in[8];
    float* out = (float*)d_out;

    cudaFuncSetAttribute(hgemm2<0>, cudaFuncAttributeMaxDynamicSharedMemorySize, SM_GEMM);
    cudaFuncSetAttribute(hgemm2<1>, cudaFuncAttributeMaxDynamicSharedMemorySize, SM_GEMM);
    cudaFuncSetAttribute(hgemm2<2>, cudaFuncAttributeMaxDynamicSharedMemorySize, SM_GEMM);
    cudaFuncSetAttribute(attn2,     cudaFuncAttributeMaxDynamicSharedMemorySize, SM_ATTN);

    // 0) fused pre-convert
    convert_all<<<10752, 256>>>(query, ipw, relw, outw);
    // 1) qkv projection
    hgemm2<1><<<dim3(24, 48), 256, SM_GEMM>>>(ipb, nullptr, Mrows, 3*En, En);
    // 2) rel-bucket value table
    hgemm2<2><<<dim3(4, 48), 256, SM_GEMM>>>(relb, nullptr, Mrows, NBn*Hn, En);
    // 3) fused HMMA flash attention
    attn2<<<dim3(4, 64, 3), 256, SM_ATTN>>>(mb, pb);
    // 4) output projection -> d_out
    hgemm2<0><<<dim3(8, 48), 256, SM_GEMM>>>(outb, out, Mrows, En, En);
}

// round 10
// speedup vs baseline: 4.9009x; 1.0726x over previous
#include <cuda_runtime.h>
#include <cuda_fp16.h>
#include <cstdint>

#define Tn    512
#define Bn    4
#define En    1024
#define Hn    16
#define HDn   64
#define NBn   32
#define TGTn  1536
#define BHn   64
#define Mrows (TGTn*Bn)   /* 6144 */
#define LOG2E 1.442695041f

// -------- scratch (static device globals) --------
__device__ __half g_x_h[(size_t)Mrows*En],    g_x_l[(size_t)Mrows*En];
__device__ __half g_ipw_h[(size_t)3*En*En],   g_ipw_l[(size_t)3*En*En];
__device__ __half g_relw_h[(size_t)NBn*Hn*En],g_relw_l[(size_t)NBn*Hn*En];
__device__ __half g_outw_h[(size_t)En*En],    g_outw_l[(size_t)En*En];
__device__ __half g_ctx_h[(size_t)Mrows*En],  g_ctx_l[(size_t)Mrows*En];
__device__ __half g_q_h[(size_t)BHn*TGTn*HDn], g_q_l[(size_t)BHn*TGTn*HDn];
__device__ __half g_k_h[(size_t)BHn*TGTn*HDn], g_k_l[(size_t)BHn*TGTn*HDn];
__device__ __half g_v_h[(size_t)BHn*TGTn*HDn], g_v_l[(size_t)BHn*TGTn*HDn];
__device__ float  g_vals[(size_t)Bn*TGTn*Hn*NBn];   // [b][tg][h][nb], pre-scaled by LOG2E

// ============================ helpers ==================================
__device__ __forceinline__ uint32_t smem_u32(const void* p) {
    uint32_t a;
    asm("{ .reg .u64 t; cvta.to.shared.u64 t, %1; cvt.u32.u64 %0, t; }"
        : "=r"(a) : "l"(p));
    return a;
}
__device__ __forceinline__ void ldsm4(uint32_t* r, uint32_t addr) {
    asm volatile("ldmatrix.sync.aligned.m8n8.x4.shared.b16 {%0,%1,%2,%3}, [%4];"
                 : "=r"(r[0]), "=r"(r[1]), "=r"(r[2]), "=r"(r[3]) : "r"(addr));
}
__device__ __forceinline__ void ldsm4t(uint32_t* r, uint32_t addr) {
    asm volatile("ldmatrix.sync.aligned.m8n8.x4.trans.shared.b16 {%0,%1,%2,%3}, [%4];"
                 : "=r"(r[0]), "=r"(r[1]), "=r"(r[2]), "=r"(r[3]) : "r"(addr));
}
__device__ __forceinline__ void mma16816(float* c, const uint32_t* a, const uint32_t* b) {
    asm volatile(
        "mma.sync.aligned.m16n8k16.row.col.f32.f16.f16.f32 "
        "{%0,%1,%2,%3}, {%4,%5,%6,%7}, {%8,%9}, {%0,%1,%2,%3};"
        : "+f"(c[0]), "+f"(c[1]), "+f"(c[2]), "+f"(c[3])
        : "r"(a[0]), "r"(a[1]), "r"(a[2]), "r"(a[3]), "r"(b[0]), "r"(b[1]));
}
__device__ __forceinline__ void cp16(uint32_t dst, const void* src) {
    asm volatile("cp.async.cg.shared.global [%0], [%1], 16;"
                 :: "r"(dst), "l"(src) : "memory");
}
#define CP_COMMIT() asm volatile("cp.async.commit_group;" ::: "memory")
#define CP_WAIT(N)  asm volatile("cp.async.wait_group %0;" :: "n"(N) : "memory")

__device__ __forceinline__ void split2(float x, float y, uint32_t& hi, uint32_t& lo) {
    __half hx = __float2half_rn(x), hy = __float2half_rn(y);
    __half lx = __float2half_rn(x - __half2float(hx));
    __half ly = __float2half_rn(y - __half2float(hy));
    __half2 h = __halves2half2(hx, hy), l = __halves2half2(lx, ly);
    hi = *(uint32_t*)&h; lo = *(uint32_t*)&l;
}
__device__ __forceinline__ float2 h2sum(uint32_t h, uint32_t l) {
    float2 a = __half22float2(*(__half2*)&h);
    float2 b = __half22float2(*(__half2*)&l);
    return make_float2(a.x + b.x, a.y + b.y);
}
__device__ __forceinline__ float ex2(float x) {
    float r;
    asm("ex2.approx.ftz.f32 %0, %1;" : "=f"(r) : "f"(x));
    return r;
}

// ---------------------------------------------------------------------------
// Fused pre-convert: f32 -> fp16 hi/lo for all four operand tensors.
// ---------------------------------------------------------------------------
__global__ __launch_bounds__(256) void convert_all(
    const float* __restrict__ q, const float* __restrict__ w1,
    const float* __restrict__ w2, const float* __restrict__ w3)
{
    int bid = blockIdx.x;
    const float* src; __half *dh, *dl; int lb;
    if (bid < 6144)      { src = q;  dh = g_x_h;    dl = g_x_l;    lb = bid; }
    else if (bid < 9216) { src = w1; dh = g_ipw_h;  dl = g_ipw_l;  lb = bid - 6144; }
    else if (bid < 9728) { src = w2; dh = g_relw_h; dl = g_relw_l; lb = bid - 9216; }
    else                 { src = w3; dh = g_outw_h; dl = g_outw_l; lb = bid - 9728; }
    int i = (lb * 256 + threadIdx.x) * 4;
    float4 v = *(const float4*)(src + i);
    uint32_t h01, l01, h23, l23;
    split2(v.x, v.y, h01, l01);
    split2(v.z, v.w, h23, l23);
    *(uint2*)(dh + i) = make_uint2(h01, h23);
    *(uint2*)(dl + i) = make_uint2(l01, l23);
}

// ---------------------------------------------------------------------------
// HMMA GEMM (fp16 split 3-pass, cp.async 2-stage): C = A*B^T + bias
// MODE 0: A=g_ctx, B=g_outw -> C (fp32)
// MODE 1: A=g_x, B=[g_ipw | g_relw] (N=3584). Cols <3072 -> q/k/v scatter
//         (q scaled 0.125*LOG2E); cols >=3072 -> g_vals (scaled LOG2E).
// ---------------------------------------------------------------------------
#define RS 80
#define MATB (128*RS)
#define STAGEB (4*MATB)
#define SM_GEMM (2*STAGEB)

template<int MODE>
__global__ __launch_bounds__(256, 2) void hgemm2(
    const float* __restrict__ bias, const float* __restrict__ bias2,
    float* __restrict__ C, int M, int N, int K)
{
    extern __shared__ __align__(16) char smem[];
    const __half* Ah = (MODE == 0) ? g_ctx_h : g_x_h;
    const __half* Al = (MODE == 0) ? g_ctx_l : g_x_l;

    int tid = threadIdx.x, lane = tid & 31, wid = tid >> 5;
    int wm = wid & 1, wn = wid >> 1;
    int m0 = blockIdx.y * 128, n0 = blockIdx.x * 128;
    uint32_t sbase = smem_u32(smem);

    const __half *Bh, *Bl; int nb0;
    if (MODE == 1 && n0 >= 3*En) { Bh = g_relw_h; Bl = g_relw_l; nb0 = n0 - 3*En; }
    else if (MODE == 1)          { Bh = g_ipw_h;  Bl = g_ipw_l;  nb0 = n0; }
    else                         { Bh = g_outw_h; Bl = g_outw_l; nb0 = n0; }

    int rowA = (lane & 7) + ((lane >> 3) & 1) * 8;
    int colA = ((lane >> 4) & 1) * 16;
    int rowB = (lane & 7) + ((lane >> 4) & 1) * 8;
    int colB = ((lane >> 3) & 1) * 16;
    uint32_t offAh = (uint32_t)((wm*64 + rowA) * RS + colA);
    uint32_t offAl = offAh + MATB;
    uint32_t offBh = (uint32_t)(2*MATB + (wn*32 + rowB) * RS + colB);
    uint32_t offBl = offBh + MATB;

    const __half* srcs[4] = {Ah, Al, Bh, Bl};

    float acc[16][4];
#pragma unroll
    for (int i = 0; i < 16; i++) { acc[i][0]=acc[i][1]=acc[i][2]=acc[i][3]=0.f; }

    auto load_stage = [&](int stage, int k0) {
        uint32_t dstb = sbase + stage * STAGEB;
#pragma unroll
        for (int it = 0; it < 8; it++) {
            int c = tid + it * 256;
            int mat = c >> 9, r = (c >> 2) & 127, cc = c & 3;
            int grow = ((mat < 2) ? m0 : nb0) + r;
            const __half* src = srcs[mat] + (size_t)grow * K + k0 + cc * 8;
            cp16(dstb + mat*MATB + r*RS + cc*16, src);
        }
        CP_COMMIT();
    };

    auto compute = [&](int stage) {
        uint32_t st = sbase + stage * STAGEB;
        uint32_t uAh = st + offAh, uAl = st + offAl;
        uint32_t uBh = st + offBh, uBl = st + offBl;
#pragma unroll
        for (int ks = 0; ks < 2; ks++) {
            uint32_t bh[4][2], bl[4][2];
#pragma unroll
            for (int np = 0; np < 2; np++) {
                uint32_t t[4];
                ldsm4(t, uBh + np*(16*RS) + ks*32);
                bh[2*np][0]=t[0]; bh[2*np][1]=t[1];
                bh[2*np+1][0]=t[2]; bh[2*np+1][1]=t[3];
                ldsm4(t, uBl + np*(16*RS) + ks*32);
                bl[2*np][0]=t[0]; bl[2*np][1]=t[1];
                bl[2*np+1][0]=t[2]; bl[2*np+1][1]=t[3];
            }
            uint32_t a[4][4];
#pragma unroll
            for (int mt = 0; mt < 4; mt++)
                ldsm4(a[mt], uAh + mt*(16*RS) + ks*32);
#pragma unroll
            for (int mt = 0; mt < 4; mt++)
#pragma unroll
                for (int nt = 0; nt < 4; nt++)
                    mma16816(acc[mt*4+nt], a[mt], bh[nt]);
#pragma unroll
            for (int mt = 0; mt < 4; mt++)
#pragma unroll
                for (int nt = 0; nt < 4; nt++)
                    mma16816(acc[mt*4+nt], a[mt], bl[nt]);
#pragma unroll
            for (int mt = 0; mt < 4; mt++)
                ldsm4(a[mt], uAl + mt*(16*RS) + ks*32);
#pragma unroll
            for (int mt = 0; mt < 4; mt++)
#pragma unroll
                for (int nt = 0; nt < 4; nt++)
                    mma16816(acc[mt*4+nt], a[mt], bh[nt]);
        }
    };

    const int nChunks = K >> 5;
    load_stage(0, 0);
    for (int c = 0; c < nChunks; c++) {
        if (c + 1 < nChunks) { load_stage((c + 1) & 1, (c + 1) * 32); CP_WAIT(1); }
        else                 { CP_WAIT(0); }
        __syncthreads();
        compute(c & 1);
        __syncthreads();
    }

#pragma unroll
    for (int mt = 0; mt < 4; mt++) {
#pragma unroll
        for (int nt = 0; nt < 4; nt++) {
            float* ac = acc[mt*4+nt];
            int nb = n0 + wn*32 + nt*8 + (lane & 3)*2;
#pragma unroll
            for (int hh = 0; hh < 2; hh++) {
                int m = m0 + wm*64 + mt*16 + (lane >> 2) + hh*8;
                if (MODE == 0) {
                    float v0 = ac[2*hh] + bias[nb], v1 = ac[2*hh+1] + bias[nb+1];
                    *(float2*)(C + (size_t)m * N + nb) = make_float2(v0, v1);
                } else {
                    int tg = m >> 2, bb = m & 3;
                    if (nb < 3*En) {
                        float v0 = ac[2*hh] + bias[nb], v1 = ac[2*hh+1] + bias[nb+1];
                        int part = nb >> 10, e = nb & 1023;
                        int hd = e >> 6, dd = e & 63;
                        if (part == 0) { v0 *= 0.125f*LOG2E; v1 *= 0.125f*LOG2E; }
                        uint32_t hi, lo;
                        split2(v0, v1, hi, lo);
                        size_t off = ((size_t)(bb*Hn + hd) * TGTn + tg) * HDn + dd;
                        __half *dh, *dl;
                        if (part == 0)      { dh = g_q_h; dl = g_q_l; }
                        else if (part == 1) { dh = g_k_h; dl = g_k_l; }
                        else                { dh = g_v_h; dl = g_v_l; }
                        *(uint32_t*)(dh + off) = hi;
                        *(uint32_t*)(dl + off) = lo;
                    } else {
                        int col = nb - 3*En;
                        float v0 = (ac[2*hh]   + bias2[col])   * LOG2E;
                        float v1 = (ac[2*hh+1] + bias2[col+1]) * LOG2E;
                        g_vals[(((size_t)bb*TGTn + tg)*Hn + (col & 15))*NBn + (col >> 4)]     = v0;
                        g_vals[(((size_t)bb*TGTn + tg)*Hn + ((col+1) & 15))*NBn + ((col+1) >> 4)] = v1;
                    }
                }
            }
        }
    }
}

// ---------------------------------------------------------------------------
// HMMA flash attention v4:
//  - Q fragments register-resident (loaded once in prologue)
//  - K/V tiles double-buffered with cp.async (stage = 36864 B)
//  - exp2-based softmax (scores pre-scaled by LOG2E upstream)
//  - causal tiles only; warp-uniform beyond-diagonal skip
//  - ngram diagonal as SIMT scalar merge
// ---------------------------------------------------------------------------
#define ARS 144
#define KVSTAGE 36864                 // 4 mats x 64 rows x 144 B
#define O_VALS (2*KVSTAGE)            // 73728
#define SM_ATTN (O_VALS + 128*32*4)   // 90112

__global__ __launch_bounds__(256, 2) void attn3(
    const int* __restrict__ main_buckets,
    const int* __restrict__ pred_buckets)
{
    extern __shared__ __align__(16) char smem[];
    float* sVals = (float*)(smem + O_VALS);
    uint32_t sbase = smem_u32(smem);

    int tid = threadIdx.x, lane = tid & 31, w = tid >> 5;
    int tileX = blockIdx.x;              // 0..3
    int bh = blockIdx.y;                 // 0..63
    int var = blockIdx.z;                // 0 main, 1..2 ngram
    int b = bh >> 4, h = bh & 15;
    int qoff = (var == 0) ? 0 : (Tn + (var - 1) * Tn);
    int t0 = tileX * 128;
    int nTiles = 2*tileX + 2;

    const __half* gkv[4] = {g_k_h, g_k_l, g_v_h, g_v_l};

    // ---- prologue: async-load K/V tile 0 into stage 0 ----
#pragma unroll
    for (int it = 0; it < 8; it++) {
        int s = tid + it * 256;
        int buf = s >> 9, r = (s >> 3) & 63, cc = s & 7;
        const __half* src = gkv[buf] + ((size_t)bh * TGTn + r) * HDn + cc * 8;
        cp16(sbase + buf*9216 + r*ARS + cc*16, src);
    }
    CP_COMMIT();

    // ---- stage Q (hi/lo) into stage-1 area, plus sVals ----
#pragma unroll
    for (int it = 0; it < 8; it++) {
        int s = tid + it * 256;
        int buf = s >> 10, r = (s >> 3) & 127, cc = s & 7;
        const __half* src = (buf ? g_q_l : g_q_h)
            + ((size_t)bh * TGTn + qoff + t0 + r) * HDn + cc * 8;
        *(uint4*)(smem + KVSTAGE + buf*18432 + r*ARS + cc*16) = *(const uint4*)src;
    }
#pragma unroll
    for (int it = 0; it < 4; it++) {
        int s = tid + it * 256;
        int r = s >> 3, cc = s & 7;
        const float* src = g_vals
            + (((size_t)b * TGTn + qoff + t0 + r) * Hn + h) * NBn + cc * 4;
        *(float4*)(sVals + r*32 + cc*4) = *(const float4*)src;
    }
    __syncthreads();

    // ---- extract Q fragments into registers ----
    int rowA = (lane & 7) + ((lane >> 3) & 1) * 8;
    int colA = ((lane >> 4) & 1) * 16;
    uint32_t aQh = sbase + KVSTAGE + (uint32_t)((16*w + rowA)*ARS + colA);
    uint32_t aQl = aQh + 18432;
    uint32_t qh[4][4], ql[4][4];
#pragma unroll
    for (int kk = 0; kk < 4; kk++) {
        ldsm4(qh[kk], aQh + kk*32);
        ldsm4(ql[kk], aQl + kk*32);
    }
    __syncthreads();    // stage-1 area free for K/V after this

    int rowB = (lane & 7) + ((lane >> 4) & 1) * 8;
    int colB = ((lane >> 3) & 1) * 16;
    int rowV = (lane & 7) + ((lane >> 3) & 1) * 8;
    int colV = ((lane >> 4) & 1) * 16;

    const int* bbase;
    int bstr;
    if (var == 0) { bbase = main_buckets + (size_t)b * Tn * Tn;      bstr = Tn;   }
    else          { bbase = pred_buckets + (size_t)b * Tn * 2 * Tn;  bstr = 2*Tn; }

    float m_[2] = {-1e30f, -1e30f}, l_[2] = {0.f, 0.f};
    float o[8][4];
#pragma unroll
    for (int j = 0; j < 8; j++) { o[j][0]=o[j][1]=o[j][2]=o[j][3]=0.f; }

    int qrow0 = (lane >> 2);
    int lim = t0 + 16*w + 15;

    for (int st = 0; st < nTiles; st++) {
        int s0 = st * 64;
        // prefetch next tile into the other stage
        if (st + 1 < nTiles) {
            int s1 = s0 + 64;
#pragma unroll
            for (int it = 0; it < 8; it++) {
                int s = tid + it * 256;
                int buf = s >> 9, r = (s >> 3) & 63, cc = s & 7;
                const __half* src = gkv[buf]
                    + ((size_t)bh * TGTn + s1 + r) * HDn + cc * 8;
                cp16(sbase + ((st+1)&1)*KVSTAGE + buf*9216 + r*ARS + cc*16, src);
            }
            CP_COMMIT();
            CP_WAIT(1);
        } else {
            CP_WAIT(0);
        }
        __syncthreads();

        if (s0 <= lim) {
            uint32_t kvb = sbase + (st & 1)*KVSTAGE;
            uint32_t aKh = kvb + (uint32_t)(rowB*ARS + colB);
            uint32_t aKl = aKh + 9216;
            uint32_t aVh = kvb + 18432 + (uint32_t)(rowV*ARS + colV);
            uint32_t aVl = aVh + 9216;

            bool jskip[8];
#pragma unroll
            for (int j = 0; j < 8; j++) jskip[j] = (s0 + 8*j > lim);

            // ---- scores ----
            float sc[8][4];
#pragma unroll
            for (int j = 0; j < 8; j++) { sc[j][0]=sc[j][1]=sc[j][2]=sc[j][3]=0.f; }
#pragma unroll
            for (int kk = 0; kk < 4; kk++) {
#pragma unroll
                for (int np = 0; np < 4; np++) {
                    if (jskip[2*np]) continue;
                    uint32_t th[4], tl[4];
                    ldsm4(th, aKh + np*(16*ARS) + kk*32);
                    ldsm4(tl, aKl + np*(16*ARS) + kk*32);
                    mma16816(sc[2*np],   qh[kk], th);
                    mma16816(sc[2*np+1], qh[kk], th+2);
                    mma16816(sc[2*np],   ql[kk], th);
                    mma16816(sc[2*np+1], ql[kk], th+2);
                    mma16816(sc[2*np],   qh[kk], tl);
                    mma16816(sc[2*np+1], qh[kk], tl+2);
                }
            }

            // ---- bias gather + causal mask ----
#pragma unroll
            for (int j = 0; j < 8; j++) {
                if (jskip[j]) continue;
                int coll = 8*j + (lane & 3)*2;
#pragma unroll
                for (int hh = 0; hh < 2; hh++) {
                    int qr = 16*w + qrow0 + 8*hh;
                    int2 bk = *(const int2*)(bbase + (size_t)(t0 + qr) * bstr + s0 + coll);
                    bool v0 = (s0 + coll)     <= (t0 + qr);
                    bool v1 = (s0 + coll + 1) <= (t0 + qr);
                    sc[j][2*hh]   = v0 ? (sc[j][2*hh]   + sVals[qr*32 + bk.x]) : -1e30f;
                    sc[j][2*hh+1] = v1 ? (sc[j][2*hh+1] + sVals[qr*32 + bk.y]) : -1e30f;
                }
            }

            // ---- online softmax (base-2) ----
#pragma unroll
            for (int hh = 0; hh < 2; hh++) {
                float rm = -1e30f;
#pragma unroll
                for (int j = 0; j < 8; j++)
                    if (!jskip[j]) rm = fmaxf(rm, fmaxf(sc[j][2*hh], sc[j][2*hh+1]));
                rm = fmaxf(rm, __shfl_xor_sync(0xffffffffu, rm, 1));
                rm = fmaxf(rm, __shfl_xor_sync(0xffffffffu, rm, 2));
                float mnew = fmaxf(m_[hh], rm);
                float scale = ex2(m_[hh] - mnew);
                float sum = 0.f;
#pragma unroll
                for (int j = 0; j < 8; j++) {
                    if (jskip[j]) { sc[j][2*hh] = 0.f; sc[j][2*hh+1] = 0.f; continue; }
                    float p0 = ex2(sc[j][2*hh]   - mnew);
                    float p1 = ex2(sc[j][2*hh+1] - mnew);
                    sc[j][2*hh] = p0; sc[j][2*hh+1] = p1;
                    sum += p0 + p1;
                }
                sum += __shfl_xor_sync(0xffffffffu, sum, 1);
                sum += __shfl_xor_sync(0xffffffffu, sum, 2);
                l_[hh] = l_[hh] * scale + sum;
                m_[hh] = mnew;
#pragma unroll
                for (int j = 0; j < 8; j++) {
                    o[j][2*hh]   *= scale;
                    o[j][2*hh+1] *= scale;
                }
            }

            // ---- O += P V ----
#pragma unroll
            for (int kk2 = 0; kk2 < 4; kk2++) {
                if (jskip[2*kk2]) continue;
                uint32_t ahi[4], alo[4];
                split2(sc[2*kk2][0],   sc[2*kk2][1],   ahi[0], alo[0]);
                split2(sc[2*kk2][2],   sc[2*kk2][3],   ahi[1], alo[1]);
                split2(sc[2*kk2+1][0], sc[2*kk2+1][1], ahi[2], alo[2]);
                split2(sc[2*kk2+1][2], sc[2*kk2+1][3], ahi[3], alo[3]);
#pragma unroll
                for (int ng = 0; ng < 4; ng++) {
                    uint32_t vh4[4], vl4[4];
                    ldsm4t(vh4, aVh + kk2*(16*ARS) + ng*32);
                    ldsm4t(vl4, aVl + kk2*(16*ARS) + ng*32);
                    mma16816(o[2*ng],   ahi, vh4);
                    mma16816(o[2*ng+1], ahi, vh4+2);
                    mma16816(o[2*ng],   alo, vh4);
                    mma16816(o[2*ng+1], alo, vh4+2);
                    mma16816(o[2*ng],   ahi, vl4);
                    mma16816(o[2*ng+1], ahi, vl4+2);
                }
            }
        }
        __syncthreads();
    }

    // ---- ngram diagonal key: SIMT scalar merge ----
    if (var != 0) {
#pragma unroll
        for (int hh = 0; hh < 2; hh++) {
            int qr = 16*w + qrow0 + 8*hh;
            int t = t0 + qr;
            size_t rowoff = ((size_t)bh * TGTn + qoff + t) * HDn;
            size_t doff = rowoff + (lane & 3) * 16;
            float dot = 0.f;
#pragma unroll
            for (int u = 0; u < 2; u++) {
                uint4 qh4 = *(const uint4*)(g_q_h + doff + u*8);
                uint4 ql4 = *(const uint4*)(g_q_l + doff + u*8);
                uint4 kh4 = *(const uint4*)(g_k_h + doff + u*8);
                uint4 kl4 = *(const uint4*)(g_k_l + doff + u*8);
                const uint32_t* qh_ = &qh4.x; const uint32_t* ql_ = &ql4.x;
                const uint32_t* kh_ = &kh4.x; const uint32_t* kl_ = &kl4.x;
#pragma unroll
                for (int c = 0; c < 4; c++) {
                    float2 qv = h2sum(qh_[c], ql_[c]);
                    float2 kv = h2sum(kh_[c], kl_[c]);
                    dot += qv.x*kv.x + qv.y*kv.y;
                }
            }
            dot += __shfl_xor_sync(0xffffffffu, dot, 1);
            dot += __shfl_xor_sync(0xffffffffu, dot, 2);
            int bkt = bbase[(size_t)t * bstr + Tn + t];
            float sd = dot + sVals[qr*32 + bkt];

            float mnew = fmaxf(m_[hh], sd);
            float scale = ex2(m_[hh] - mnew);
            float pd = ex2(sd - mnew);
            l_[hh] = l_[hh] * scale + pd;
            m_[hh] = mnew;
#pragma unroll
            for (int j = 0; j < 8; j++) {
                int col = 8*j + (lane & 3)*2;
                uint32_t vh = *(const uint32_t*)(g_v_h + rowoff + col);
                uint32_t vl = *(const uint32_t*)(g_v_l + rowoff + col);
                float2 vv = h2sum(vh, vl);
                o[j][2*hh]   = o[j][2*hh]   * scale + pd * vv.x;
                o[j][2*hh+1] = o[j][2*hh+1] * scale + pd * vv.y;
            }
        }
    }

    // ---- epilogue: ctx (fp16 hi/lo) = O / l ----
#pragma unroll
    for (int hh = 0; hh < 2; hh++) {
        int qr = 16*w + qrow0 + 8*hh;
        int tg = qoff + t0 + qr;
        float inv = 1.0f / l_[hh];
#pragma unroll
        for (int j = 0; j < 8; j++) {
            int col = 8*j + (lane & 3)*2;
            float x0 = o[j][2*hh] * inv, x1 = o[j][2*hh+1] * inv;
            uint32_t hi, lo;
            split2(x0, x1, hi, lo);
            size_t off = ((size_t)tg * Bn + b) * En + h * HDn + col;
            *(uint32_t*)(g_ctx_h + off) = hi;
            *(uint32_t*)(g_ctx_l + off) = lo;
        }
    }
}

// ---------------------------------------------------------------------------
extern "C" void kernel_launch(void* const* d_in, const int* in_sizes, int n_in,
                              void* d_out, int out_size) {
    const float* query = (const float*)d_in[0];
    const float* ipw   = (const float*)d_in[1];
    const float* ipb   = (const float*)d_in[2];
    const float* relw  = (const float*)d_in[3];
    const float* relb  = (const float*)d_in[4];
    const float* outw  = (const float*)d_in[5];
    const float* outb  = (const float*)d_in[6];
    const int*   mb    = (const int*)d_in[7];
    const int*   pb    = (const int*)d_in[8];
    float* out = (float*)d_out;

    cudaFuncSetAttribute(hgemm2<0>, cudaFuncAttributeMaxDynamicSharedMemorySize, SM_GEMM);
    cudaFuncSetAttribute(hgemm2<1>, cudaFuncAttributeMaxDynamicSharedMemorySize, SM_GEMM);
    cudaFuncSetAttribute(attn3,     cudaFuncAttributeMaxDynamicSharedMemorySize, SM_ATTN);

    // 0) fused pre-convert
    convert_all<<<10752, 256>>>(query, ipw, relw, outw);
    // 1) qkv + rel-vals projection (merged, N = 3072 + 512)
    hgemm2<1><<<dim3(28, 48), 256, SM_GEMM>>>(ipb, relb, nullptr, Mrows, 3*En + NBn*Hn, En);
    // 2) fused HMMA flash attention
    attn3<<<dim3(4, 64, 3), 256, SM_ATTN>>>(mb, pb);
    // 3) output projection -> d_out
    hgemm2<0><<<dim3(8, 48), 256, SM_GEMM>>>(outb, nullptr, out, Mrows, En, En);
}